// round 12
// baseline (speedup 1.0000x reference)
#include <cuda_runtime.h>
#include <cuda_bf16.h>
#include <cstdint>

#define NNODE 170
#define MPAD  176          // node dim padded to 11 m-tiles of 16
#define SA    184          // adj smem row stride (elems)
#define SB    72           // X/Y1 smem row stride (elems)
#define TSEQ  64
#define CIN   64
#define COUT  64
#define BATCH 32
#define NT    (NNODE*TSEQ)          // 10880 = 85 * 128
#define BSTRIDE (CIN*NT)
#define NITEMS (BATCH*CIN)          // 2048
#define NODE_GRID 148

#define KCH   192          // channel-stage K = 3*CIN
#define SW    200          // W image row stride (elems)
#define SC    136          // chan B tile row stride (elems)
#define PTILE 128          // pos per chan CTA

typedef unsigned long long u64;

// ---------------- device scratch (no allocs allowed) -----------------------
__device__ float g_Y1[BATCH*CIN*NT];
__device__ float g_Y2[BATCH*CIN*NT];
__device__ __align__(16) __nv_bfloat16 g_adjh[MPAD*SA]; // padded [176][184]
__device__ __align__(16) __nv_bfloat16 g_adjl[MPAD*SA];
__device__ __align__(16) __nv_bfloat16 g_Wh[COUT*SW];   // [o][k=s*64+c] hi
__device__ __align__(16) __nv_bfloat16 g_Wl[COUT*SW];   // lo

// ---------------- node smem map (bytes) -------------------------------------
#define AH_OFF 0                        // 176*184*2 = 64768
#define AL_OFF 64768
#define BH_OFF 129536                   // 176*72*2  = 25344
#define BL_OFF 154880
#define NODE_SMEM 180224

// ---------------- chan smem map (bytes) -------------------------------------
#define WH_OFF 0                        // 64*200*2 = 25600
#define WL_OFF 25600
#define CBH_OFF 51200                   // 192*136*2 = 52224
#define CBL_OFF 103424
#define CHAN_SMEM 155648

// ---------------- helpers ---------------------------------------------------
__device__ __forceinline__ uint32_t smem_u32(const void* p) {
    uint32_t a;
    asm("{ .reg .u64 t; cvta.to.shared.u64 t, %1; cvt.u32.u64 %0, t; }"
        : "=r"(a) : "l"(p));
    return a;
}

#define LDSM_X4(r, addr) \
    asm volatile("ldmatrix.sync.aligned.m8n8.x4.shared.b16 {%0,%1,%2,%3}, [%4];" \
        : "=r"((r)[0]), "=r"((r)[1]), "=r"((r)[2]), "=r"((r)[3]) : "r"(addr))
#define LDSM_X4T(r, addr) \
    asm volatile("ldmatrix.sync.aligned.m8n8.x4.trans.shared.b16 {%0,%1,%2,%3}, [%4];" \
        : "=r"((r)[0]), "=r"((r)[1]), "=r"((r)[2]), "=r"((r)[3]) : "r"(addr))

#define MMA_BF16(d, a, b0, b1) \
    asm volatile("mma.sync.aligned.m16n8k16.row.col.f32.bf16.bf16.f32 " \
        "{%0,%1,%2,%3}, {%4,%5,%6,%7}, {%8,%9}, {%0,%1,%2,%3};" \
        : "+f"((d)[0]), "+f"((d)[1]), "+f"((d)[2]), "+f"((d)[3]) \
        : "r"((a)[0]), "r"((a)[1]), "r"((a)[2]), "r"((a)[3]), "r"(b0), "r"(b1))

__device__ __forceinline__ void split_bf16(float v, __nv_bfloat16& h, __nv_bfloat16& l) {
    h = __float2bfloat16(v);
    l = __float2bfloat16(v - __bfloat162float(h));
}

// ---------------------------------------------------------------------------
// Prep kernels
// ---------------------------------------------------------------------------
__global__ void k_prep_w(const float* __restrict__ W)
{
    int i = blockIdx.x * 256 + threadIdx.x;     // over 64*SW
    if (i >= COUT*SW) return;
    int o = i / SW, k = i % SW;
    float v = 0.0f;
    if (k < KCH) {
        int s = k >> 6, c = k & 63;
        v = W[o*KCH + c*3 + s];
    }
    __nv_bfloat16 h, l;
    split_bf16(v, h, l);
    g_Wh[i] = h;
    g_Wl[i] = l;
}

__global__ void k_prep_adj(const float* __restrict__ adj)
{
    int i = blockIdx.x * 256 + threadIdx.x;
    if (i >= MPAD*SA) return;
    int q = i / SA, k = i % SA;
    float a = (q < NNODE && k < NNODE) ? adj[q*NNODE + k] : 0.0f;
    __nv_bfloat16 h, l;
    split_bf16(a, h, l);
    g_adjh[i] = h;
    g_adjl[i] = l;
}

// ---------------------------------------------------------------------------
// Node GEMM (512-thread): warp w owns units (mtA, nh) and, for w<6,
// (mtB = 8 + (w>>1), nh). Both units share the same 32-col n-half -> B
// fragments loaded once. acc[u][nt][4].
// ---------------------------------------------------------------------------
__device__ __forceinline__ void gemm512(uint32_t aH, uint32_t aL,
                                        uint32_t bH, uint32_t bL,
                                        int w, int lane, float acc[2][4][4])
{
    #pragma unroll
    for (int u = 0; u < 2; u++)
        #pragma unroll
        for (int n = 0; n < 4; n++)
            #pragma unroll
            for (int p = 0; p < 4; p++) acc[u][n][p] = 0.0f;

    const int nh   = w & 1;
    const int mtA  = w >> 1;
    const bool hasB = (w < 6);
    const int mtB  = 8 + (w >> 1);
    const int brow = lane & 15;
    const int bcol = (lane >> 4) * 8;

    for (int k0 = 0; k0 < MPAD; k0 += 16) {
        uint32_t bh[2][4], bl[2][4];
        #pragma unroll
        for (int gB = 0; gB < 2; gB++) {
            const uint32_t bb =
                (uint32_t)((k0 + brow)*SB + nh*32 + gB*16 + bcol) * 2;
            LDSM_X4T(bh[gB], bH + bb);
            LDSM_X4T(bl[gB], bL + bb);
        }
        uint32_t ah[4], al[4];
        const uint32_t abA = (uint32_t)((mtA*16 + brow)*SA + k0 + bcol) * 2;
        LDSM_X4(ah, aH + abA);
        LDSM_X4(al, aL + abA);
        #pragma unroll
        for (int gB = 0; gB < 2; gB++)
            #pragma unroll
            for (int s = 0; s < 2; s++) {
                float* d = acc[0][gB*2 + s];
                MMA_BF16(d, ah, bh[gB][s*2], bh[gB][s*2+1]);
                MMA_BF16(d, ah, bl[gB][s*2], bl[gB][s*2+1]);
                MMA_BF16(d, al, bh[gB][s*2], bh[gB][s*2+1]);
            }
        if (hasB) {
            uint32_t ah2[4], al2[4];
            const uint32_t abB = (uint32_t)((mtB*16 + brow)*SA + k0 + bcol) * 2;
            LDSM_X4(ah2, aH + abB);
            LDSM_X4(al2, aL + abB);
            #pragma unroll
            for (int gB = 0; gB < 2; gB++)
                #pragma unroll
                for (int s = 0; s < 2; s++) {
                    float* d = acc[1][gB*2 + s];
                    MMA_BF16(d, ah2, bh[gB][s*2], bh[gB][s*2+1]);
                    MMA_BF16(d, ah2, bl[gB][s*2], bl[gB][s*2+1]);
                    MMA_BF16(d, al2, bh[gB][s*2], bh[gB][s*2+1]);
                }
        }
    }
}

// ---------------------------------------------------------------------------
// Persistent node stage (unchanged from R9): grid=148 x 512 threads
// ---------------------------------------------------------------------------
__global__ __launch_bounds__(512, 1) void k_node_pers(const float* __restrict__ x)
{
    extern __shared__ char smem[];
    const uint32_t sbase = smem_u32(smem);
    const uint32_t aH = sbase + AH_OFF, aL = sbase + AL_OFF;
    const uint32_t bHo = sbase + BH_OFF, bLo = sbase + BL_OFF;
    __nv_bfloat16* sBH = (__nv_bfloat16*)(smem + BH_OFF);
    __nv_bfloat16* sBL = (__nv_bfloat16*)(smem + BL_OFF);

    const int tid  = threadIdx.x;
    const int w    = tid >> 5;
    const int lane = tid & 31;
    const int g    = lane >> 2;
    const int c2   = (lane & 3) * 2;
    const int nh   = w & 1;

    {
        const float4* gh = (const float4*)g_adjh;
        const float4* gl = (const float4*)g_adjl;
        float4* dh = (float4*)(smem + AH_OFF);
        float4* dl = (float4*)(smem + AL_OFF);
        for (int i = tid; i < (MPAD*SA*2)/16; i += 512) { dh[i] = gh[i]; dl[i] = gl[i]; }
    }
    for (int i = tid; i < (MPAD - NNODE)*SB; i += 512) {
        const int idx = NNODE*SB + i;
        sBH[idx] = __float2bfloat16(0.f);
        sBL[idx] = __float2bfloat16(0.f);
    }

    float acc[2][4][4];

    for (int it = blockIdx.x; it < NITEMS; it += NODE_GRID) {
        const float* Xg = x + (size_t)it * NT;
        float* Y1g = g_Y1 + (size_t)it * NT;
        float* Y2g = g_Y2 + (size_t)it * NT;

        __syncthreads();
        for (int idx = tid; idx < NNODE*(TSEQ/4); idx += 512) {
            const int n  = idx >> 4;
            const int t4 = idx & 15;
            const float4 v = __ldg((const float4*)(Xg + n*TSEQ) + t4);
            __nv_bfloat16 h0,l0,h1,l1,h2,l2,h3,l3;
            split_bf16(v.x, h0, l0); split_bf16(v.y, h1, l1);
            split_bf16(v.z, h2, l2); split_bf16(v.w, h3, l3);
            __nv_bfloat162 hh[2] = { {h0,h1}, {h2,h3} };
            __nv_bfloat162 ll[2] = { {l0,l1}, {l2,l3} };
            *(uint2*)(sBH + n*SB + t4*4) = *(uint2*)hh;
            *(uint2*)(sBL + n*SB + t4*4) = *(uint2*)ll;
        }
        __syncthreads();

        gemm512(aH, aL, bHo, bLo, w, lane, acc);
        __syncthreads();

        #pragma unroll
        for (int u = 0; u < 2; u++) {
            const int mt = u ? 8 + (w >> 1) : (w >> 1);
            if (u == 0 || w < 6) {
                #pragma unroll
                for (int nt = 0; nt < 4; nt++) {
                    const int t = nh*32 + nt*8 + c2;
                    #pragma unroll
                    for (int rr = 0; rr < 2; rr++) {
                        const int q = mt*16 + g + rr*8;
                        const float v0 = acc[u][nt][rr*2];
                        const float v1 = acc[u][nt][rr*2+1];
                        if (q < NNODE) {
                            float2 o; o.x = v0; o.y = v1;
                            *(float2*)(Y1g + q*TSEQ + t) = o;
                        }
                        __nv_bfloat162 h2, l2;
                        split_bf16(v0, h2.x, l2.x);
                        split_bf16(v1, h2.y, l2.y);
                        *(__nv_bfloat162*)(sBH + q*SB + t) = h2;
                        *(__nv_bfloat162*)(sBL + q*SB + t) = l2;
                    }
                }
            }
        }
        __syncthreads();

        gemm512(aH, aL, bHo, bLo, w, lane, acc);

        #pragma unroll
        for (int u = 0; u < 2; u++) {
            const int mt = u ? 8 + (w >> 1) : (w >> 1);
            if (u == 0 || w < 6) {
                #pragma unroll
                for (int nt = 0; nt < 4; nt++) {
                    const int t = nh*32 + nt*8 + c2;
                    #pragma unroll
                    for (int rr = 0; rr < 2; rr++) {
                        const int q = mt*16 + g + rr*8;
                        if (q < NNODE) {
                            const float2 xv = *(const float2*)(Xg + q*TSEQ + t);
                            float2 o;
                            o.x = 2.f*acc[u][nt][rr*2]   - xv.x;
                            o.y = 2.f*acc[u][nt][rr*2+1] - xv.y;
                            *(float2*)(Y2g + q*TSEQ + t) = o;
                        }
                    }
                }
            }
        }
    }
}

// ---------------------------------------------------------------------------
// Channel stage via HMMA — 512 threads, 16 warps = 4(m) x 4(n).
// Warp owns one m16 tile (16 o's) x 32 pos.
// ---------------------------------------------------------------------------
__global__ __launch_bounds__(512, 1) void k_chan_hmma(const float* __restrict__ x,
                                                      const float* __restrict__ bias,
                                                      float* __restrict__ out)
{
    extern __shared__ char smem[];
    const uint32_t sbase = smem_u32(smem);
    const uint32_t wH = sbase + WH_OFF, wL = sbase + WL_OFF;
    const uint32_t cH = sbase + CBH_OFF, cL = sbase + CBL_OFF;
    __nv_bfloat16* sBH = (__nv_bfloat16*)(smem + CBH_OFF);
    __nv_bfloat16* sBL = (__nv_bfloat16*)(smem + CBL_OFF);

    const int tid  = threadIdx.x;
    const int w    = tid >> 5;
    const int lane = tid & 31;
    const int wm   = w & 3;          // m-tile 0..3 (o = wm*16 ..)
    const int wn   = w >> 2;         // n quarter: 32 pos each
    const int b    = blockIdx.y;
    const int p0   = blockIdx.x * PTILE;

    const float* srcs[3];
    srcs[0] = x    + (size_t)b * BSTRIDE;
    srcs[1] = g_Y1 + (size_t)b * BSTRIDE;
    srcs[2] = g_Y2 + (size_t)b * BSTRIDE;

    // ---- stage W hi/lo images (L2-resident) ----
    {
        const float4* gh = (const float4*)g_Wh;
        const float4* gl = (const float4*)g_Wl;
        float4* dh = (float4*)(smem + WH_OFF);
        float4* dl = (float4*)(smem + WL_OFF);
        for (int i = tid; i < (COUT*SW*2)/16; i += 512) { dh[i] = gh[i]; dl[i] = gl[i]; }
    }
    // ---- stage B tile [192][128] f32 -> bf16 hi/lo ----
    for (int idx = tid; idx < KCH*(PTILE/4); idx += 512) {
        const int k  = idx >> 5;
        const int p4 = idx & 31;
        const float4 v = *(const float4*)(srcs[k >> 6] + (size_t)(k & 63)*NT + p0 + p4*4);
        __nv_bfloat16 h0,l0,h1,l1,h2,l2,h3,l3;
        split_bf16(v.x, h0, l0); split_bf16(v.y, h1, l1);
        split_bf16(v.z, h2, l2); split_bf16(v.w, h3, l3);
        __nv_bfloat162 hh[2] = { {h0,h1}, {h2,h3} };
        __nv_bfloat162 ll[2] = { {l0,l1}, {l2,l3} };
        *(uint2*)(sBH + k*SC + p4*4) = *(uint2*)hh;
        *(uint2*)(sBL + k*SC + p4*4) = *(uint2*)ll;
    }
    __syncthreads();

    // ---- GEMM: M=64, N=128, K=192, 3 split passes; warp = 1 m-tile x 32 pos
    float acc[4][4];
    #pragma unroll
    for (int ni = 0; ni < 4; ni++)
        #pragma unroll
        for (int p = 0; p < 4; p++) acc[ni][p] = 0.0f;

    const int brow_l = lane & 15;
    const int bcol_l = (lane >> 4) * 8;

    for (int k0 = 0; k0 < KCH; k0 += 16) {
        uint32_t bh[2][4], bl[2][4];
        #pragma unroll
        for (int gB = 0; gB < 2; gB++) {
            const uint32_t bb =
                (uint32_t)((k0 + brow_l)*SC + wn*32 + gB*16 + bcol_l) * 2;
            LDSM_X4T(bh[gB], cH + bb);
            LDSM_X4T(bl[gB], cL + bb);
        }
        uint32_t ah[4], al[4];
        const uint32_t ab =
            (uint32_t)((wm*16 + brow_l)*SW + k0 + bcol_l) * 2;
        LDSM_X4(ah, wH + ab);
        LDSM_X4(al, wL + ab);
        #pragma unroll
        for (int gB = 0; gB < 2; gB++)
            #pragma unroll
            for (int s = 0; s < 2; s++) {
                float* d = acc[gB*2 + s];
                MMA_BF16(d, ah, bh[gB][s*2], bh[gB][s*2+1]);
                MMA_BF16(d, ah, bl[gB][s*2], bl[gB][s*2+1]);
                MMA_BF16(d, al, bh[gB][s*2], bh[gB][s*2+1]);
            }
    }

    // ---- epilogue: bias + store ----
    const int g  = lane >> 2;
    const int c2 = (lane & 3) * 2;
    float* outb = out + (size_t)b * (COUT*(size_t)NT);
    #pragma unroll
    for (int rr = 0; rr < 2; rr++) {
        const int o = wm*16 + g + rr*8;
        const float bv = __ldg(bias + o);
        #pragma unroll
        for (int ni = 0; ni < 4; ni++) {
            const int pos = p0 + wn*32 + ni*8 + c2;
            float2 r;
            r.x = acc[ni][rr*2]   + bv;
            r.y = acc[ni][rr*2+1] + bv;
            *(float2*)(outb + (size_t)o*NT + pos) = r;
        }
    }
}

// ---------------------------------------------------------------------------
extern "C" void kernel_launch(void* const* d_in, const int* in_sizes, int n_in,
                              void* d_out, int out_size)
{
    const float* x    = (const float*)d_in[0];
    const float* adj  = (const float*)d_in[1];
    const float* W    = (const float*)d_in[2];
    const float* bias = (const float*)d_in[3];
    float* out = (float*)d_out;

    cudaFuncSetAttribute(k_node_pers, cudaFuncAttributeMaxDynamicSharedMemorySize,
                         NODE_SMEM);
    cudaFuncSetAttribute(k_chan_hmma, cudaFuncAttributeMaxDynamicSharedMemorySize,
                         CHAN_SMEM);

    k_prep_w<<<(COUT*SW + 255)/256, 256>>>(W);
    k_prep_adj<<<(MPAD*SA + 255)/256, 256>>>(adj);
    k_node_pers<<<NODE_GRID, 512, NODE_SMEM>>>(x);
    dim3 cgrid(NT/PTILE, BATCH);    // (85, 32)
    k_chan_hmma<<<cgrid, 512, CHAN_SMEM>>>(x, bias, out);
}

// round 13
// speedup vs baseline: 1.4255x; 1.4255x over previous
#include <cuda_runtime.h>
#include <cuda_bf16.h>
#include <cstdint>

#define NNODE 170
#define MPAD  176          // node dim padded to 11 m-tiles of 16
#define SA    184          // adj smem row stride (elems)
#define SB2   136          // node B tile row stride (elems), 128 cols used
#define TSEQ  64
#define CIN   64
#define COUT  64
#define BATCH 32
#define NT    (NNODE*TSEQ)          // 10880 = 85 * 128
#define BSTRIDE (CIN*NT)
#define NITEMS (BATCH*CIN)          // 2048
#define NPAIR  (NITEMS/2)           // 1024
#define NODE_GRID 148

#define KCH   192          // channel-stage K = 3*CIN
#define SW    200          // W image row stride (elems)
#define SC    136          // chan B tile row stride (elems)
#define PTILE 128          // pos per chan CTA

typedef unsigned long long u64;

// ---------------- device scratch (no allocs allowed) -----------------------
__device__ float g_Y1[BATCH*CIN*NT];
__device__ float g_Y2[BATCH*CIN*NT];
__device__ __align__(16) __nv_bfloat16 g_adjh[MPAD*SA]; // padded [176][184]
__device__ __align__(16) __nv_bfloat16 g_adjl[MPAD*SA];
__device__ __align__(16) __nv_bfloat16 g_Wh[COUT*SW];   // [o][k=s*64+c] hi
__device__ __align__(16) __nv_bfloat16 g_Wl[COUT*SW];   // lo

// ---------------- node smem map (bytes) -------------------------------------
#define AH_OFF 0                        // 176*184*2 = 64768
#define AL_OFF 64768
#define BH_OFF 129536                   // 176*136*2 = 47872
#define BL_OFF 177408
#define NODE_SMEM 225280                // <= 227 KB cap

// ---------------- chan smem map (bytes) -------------------------------------
#define WH_OFF 0                        // 64*200*2 = 25600
#define WL_OFF 25600
#define CBH_OFF 51200                   // 192*136*2 = 52224
#define CBL_OFF 103424
#define CHAN_SMEM 155648

// ---------------- helpers ---------------------------------------------------
__device__ __forceinline__ uint32_t smem_u32(const void* p) {
    uint32_t a;
    asm("{ .reg .u64 t; cvta.to.shared.u64 t, %1; cvt.u32.u64 %0, t; }"
        : "=r"(a) : "l"(p));
    return a;
}

#define LDSM_X4(r, addr) \
    asm volatile("ldmatrix.sync.aligned.m8n8.x4.shared.b16 {%0,%1,%2,%3}, [%4];" \
        : "=r"((r)[0]), "=r"((r)[1]), "=r"((r)[2]), "=r"((r)[3]) : "r"(addr))
#define LDSM_X4T(r, addr) \
    asm volatile("ldmatrix.sync.aligned.m8n8.x4.trans.shared.b16 {%0,%1,%2,%3}, [%4];" \
        : "=r"((r)[0]), "=r"((r)[1]), "=r"((r)[2]), "=r"((r)[3]) : "r"(addr))

#define MMA_BF16(d, a, b0, b1) \
    asm volatile("mma.sync.aligned.m16n8k16.row.col.f32.bf16.bf16.f32 " \
        "{%0,%1,%2,%3}, {%4,%5,%6,%7}, {%8,%9}, {%0,%1,%2,%3};" \
        : "+f"((d)[0]), "+f"((d)[1]), "+f"((d)[2]), "+f"((d)[3]) \
        : "r"((a)[0]), "r"((a)[1]), "r"((a)[2]), "r"((a)[3]), "r"(b0), "r"(b1))

__device__ __forceinline__ void split_bf16(float v, __nv_bfloat16& h, __nv_bfloat16& l) {
    h = __float2bfloat16(v);
    l = __float2bfloat16(v - __bfloat162float(h));
}

// ---------------------------------------------------------------------------
// Prep kernels
// ---------------------------------------------------------------------------
__global__ void k_prep_w(const float* __restrict__ W)
{
    int i = blockIdx.x * 256 + threadIdx.x;     // over 64*SW
    if (i >= COUT*SW) return;
    int o = i / SW, k = i % SW;
    float v = 0.0f;
    if (k < KCH) {
        int s = k >> 6, c = k & 63;
        v = W[o*KCH + c*3 + s];
    }
    __nv_bfloat16 h, l;
    split_bf16(v, h, l);
    g_Wh[i] = h;
    g_Wl[i] = l;
}

__global__ void k_prep_adj(const float* __restrict__ adj)
{
    int i = blockIdx.x * 256 + threadIdx.x;
    if (i >= MPAD*SA) return;
    int q = i / SA, k = i % SA;
    float a = (q < NNODE && k < NNODE) ? adj[q*NNODE + k] : 0.0f;
    __nv_bfloat16 h, l;
    split_bf16(a, h, l);
    g_adjh[i] = h;
    g_adjl[i] = l;
}

// ---------------------------------------------------------------------------
// Node GEMM, 2-item wide (N=128): 16 warps, warp w owns n-chunk (w&3)*32 and
// m-tiles {w>>2, 4+(w>>2), 8+(w>>2) if <11}. B frags amortized over 3 m-tiles.
// ---------------------------------------------------------------------------
__device__ __forceinline__ void gemm_n128(uint32_t aH, uint32_t aL,
                                          uint32_t bH, uint32_t bL,
                                          int w, int lane, float acc[3][4][4])
{
    #pragma unroll
    for (int u = 0; u < 3; u++)
        #pragma unroll
        for (int n = 0; n < 4; n++)
            #pragma unroll
            for (int p = 0; p < 4; p++) acc[u][n][p] = 0.0f;

    const int nq   = w & 3;
    const int mt0  = w >> 2;            // 0..3
    const bool hasC = (mt0 < 3);        // third m-tile 8+mt0 < 11
    const int brow = lane & 15;
    const int bcol = (lane >> 4) * 8;

    for (int k0 = 0; k0 < MPAD; k0 += 16) {
        uint32_t bh[2][4], bl[2][4];
        #pragma unroll
        for (int gB = 0; gB < 2; gB++) {
            const uint32_t bb =
                (uint32_t)((k0 + brow)*SB2 + nq*32 + gB*16 + bcol) * 2;
            LDSM_X4T(bh[gB], bH + bb);
            LDSM_X4T(bl[gB], bL + bb);
        }
        #pragma unroll
        for (int u = 0; u < 3; u++) {
            if (u == 2 && !hasC) break;
            const int mt = u*4 + mt0;
            uint32_t ah[4], al[4];
            const uint32_t ab = (uint32_t)((mt*16 + brow)*SA + k0 + bcol) * 2;
            LDSM_X4(ah, aH + ab);
            LDSM_X4(al, aL + ab);
            #pragma unroll
            for (int gB = 0; gB < 2; gB++)
                #pragma unroll
                for (int s = 0; s < 2; s++) {
                    float* d = acc[u][gB*2 + s];
                    MMA_BF16(d, ah, bh[gB][s*2], bh[gB][s*2+1]);
                    MMA_BF16(d, ah, bl[gB][s*2], bl[gB][s*2+1]);
                    MMA_BF16(d, al, bh[gB][s*2], bh[gB][s*2+1]);
                }
        }
    }
}

// ---------------------------------------------------------------------------
// Persistent node stage, 2 items per iteration: grid=148 x 512 threads.
//   Y1 = adj @ [X0|X1] ;  Y2 = 2*adj @ [Y1] - [X0|X1]
// ---------------------------------------------------------------------------
__global__ __launch_bounds__(512, 1) void k_node_pers(const float* __restrict__ x)
{
    extern __shared__ char smem[];
    const uint32_t sbase = smem_u32(smem);
    const uint32_t aH = sbase + AH_OFF, aL = sbase + AL_OFF;
    const uint32_t bHo = sbase + BH_OFF, bLo = sbase + BL_OFF;
    __nv_bfloat16* sBH = (__nv_bfloat16*)(smem + BH_OFF);
    __nv_bfloat16* sBL = (__nv_bfloat16*)(smem + BL_OFF);

    const int tid  = threadIdx.x;
    const int w    = tid >> 5;
    const int lane = tid & 31;
    const int g    = lane >> 2;
    const int c2   = (lane & 3) * 2;
    const int nq   = w & 3;
    const int mt0  = w >> 2;
    const bool hasC = (mt0 < 3);
    const int item = nq >> 1;            // this warp's cols are all in one item
    const int tbase = nq*32 - item*64;   // col -> t offset within item

    // ---- stage adj hi/lo once ----
    {
        const float4* gh = (const float4*)g_adjh;
        const float4* gl = (const float4*)g_adjl;
        float4* dh = (float4*)(smem + AH_OFF);
        float4* dl = (float4*)(smem + AL_OFF);
        for (int i = tid; i < (MPAD*SA*2)/16; i += 512) { dh[i] = gh[i]; dl[i] = gl[i]; }
    }
    // zero B pad rows once (epilogue-1 re-zeros them every iteration)
    for (int i = tid; i < (MPAD - NNODE)*SB2; i += 512) {
        const int idx = NNODE*SB2 + i;
        sBH[idx] = __float2bfloat16(0.f);
        sBL[idx] = __float2bfloat16(0.f);
    }

    float acc[3][4][4];

    for (int it2 = blockIdx.x; it2 < NPAIR; it2 += NODE_GRID) {
        const float* Xg0 = x + (size_t)(it2*2) * NT;
        const float* Xg  = Xg0 + (size_t)item * NT;   // this warp's item
        float* Y1g = g_Y1 + (size_t)(it2*2 + item) * NT;
        float* Y2g = g_Y2 + (size_t)(it2*2 + item) * NT;

        __syncthreads();     // prior GEMM2 readers done before B overwrite
        // ---- stage X of both items: B[n][col], col = itm*64 + t ----
        for (int idx = tid; idx < NNODE*32; idx += 512) {
            const int n   = idx >> 5;
            const int c4  = idx & 31;          // float4-col 0..31
            const int itm = c4 >> 4;
            const int t4  = c4 & 15;
            const float4 v = __ldg((const float4*)(Xg0 + (size_t)itm*NT + n*TSEQ) + t4);
            __nv_bfloat16 h0,l0,h1,l1,h2,l2,h3,l3;
            split_bf16(v.x, h0, l0); split_bf16(v.y, h1, l1);
            split_bf16(v.z, h2, l2); split_bf16(v.w, h3, l3);
            __nv_bfloat162 hh[2] = { {h0,h1}, {h2,h3} };
            __nv_bfloat162 ll[2] = { {l0,l1}, {l2,l3} };
            *(uint2*)(sBH + n*SB2 + c4*4) = *(uint2*)hh;
            *(uint2*)(sBL + n*SB2 + c4*4) = *(uint2*)ll;
        }
        __syncthreads();

        // ======== GEMM 1: Y1 = adj @ [X0|X1] ========
        gemm_n128(aH, aL, bHo, bLo, w, lane, acc);
        __syncthreads();     // everyone done reading B

        // epilogue 1: write Y1 f32 + resplit into B
        #pragma unroll
        for (int u = 0; u < 3; u++) {
            if (u == 2 && !hasC) break;
            const int mt = u*4 + mt0;
            #pragma unroll
            for (int nt = 0; nt < 4; nt++) {
                const int col = nq*32 + nt*8 + c2;
                const int t   = tbase + nt*8 + c2;
                #pragma unroll
                for (int rr = 0; rr < 2; rr++) {
                    const int q = mt*16 + g + rr*8;
                    const float v0 = acc[u][nt][rr*2];
                    const float v1 = acc[u][nt][rr*2+1];
                    if (q < NNODE) {
                        float2 o; o.x = v0; o.y = v1;
                        *(float2*)(Y1g + q*TSEQ + t) = o;
                    }
                    __nv_bfloat162 h2, l2;
                    split_bf16(v0, h2.x, l2.x);
                    split_bf16(v1, h2.y, l2.y);
                    *(__nv_bfloat162*)(sBH + q*SB2 + col) = h2;
                    *(__nv_bfloat162*)(sBL + q*SB2 + col) = l2;
                }
            }
        }
        __syncthreads();

        // ======== GEMM 2: Y2 = 2*adj @ Y1 - X ========
        gemm_n128(aH, aL, bHo, bLo, w, lane, acc);

        #pragma unroll
        for (int u = 0; u < 3; u++) {
            if (u == 2 && !hasC) break;
            const int mt = u*4 + mt0;
            #pragma unroll
            for (int nt = 0; nt < 4; nt++) {
                const int t = tbase + nt*8 + c2;
                #pragma unroll
                for (int rr = 0; rr < 2; rr++) {
                    const int q = mt*16 + g + rr*8;
                    if (q < NNODE) {
                        const float2 xv = *(const float2*)(Xg + q*TSEQ + t);
                        float2 o;
                        o.x = 2.f*acc[u][nt][rr*2]   - xv.x;
                        o.y = 2.f*acc[u][nt][rr*2+1] - xv.y;
                        *(float2*)(Y2g + q*TSEQ + t) = o;
                    }
                }
            }
        }
    }
}

// ---------------------------------------------------------------------------
// Channel stage via HMMA — exact R8 version (256 threads, 8 warps = 2m x 4n)
// ---------------------------------------------------------------------------
__global__ __launch_bounds__(256, 1) void k_chan_hmma(const float* __restrict__ x,
                                                      const float* __restrict__ bias,
                                                      float* __restrict__ out)
{
    extern __shared__ char smem[];
    const uint32_t sbase = smem_u32(smem);
    const uint32_t wH = sbase + WH_OFF, wL = sbase + WL_OFF;
    const uint32_t cH = sbase + CBH_OFF, cL = sbase + CBL_OFF;
    __nv_bfloat16* sBH = (__nv_bfloat16*)(smem + CBH_OFF);
    __nv_bfloat16* sBL = (__nv_bfloat16*)(smem + CBL_OFF);

    const int tid  = threadIdx.x;
    const int w    = tid >> 5;
    const int lane = tid & 31;
    const int wm   = w & 1;
    const int wn   = w >> 1;
    const int b    = blockIdx.y;
    const int p0   = blockIdx.x * PTILE;

    const float* srcs[3];
    srcs[0] = x    + (size_t)b * BSTRIDE;
    srcs[1] = g_Y1 + (size_t)b * BSTRIDE;
    srcs[2] = g_Y2 + (size_t)b * BSTRIDE;

    {
        const float4* gh = (const float4*)g_Wh;
        const float4* gl = (const float4*)g_Wl;
        float4* dh = (float4*)(smem + WH_OFF);
        float4* dl = (float4*)(smem + WL_OFF);
        for (int i = tid; i < (COUT*SW*2)/16; i += 256) { dh[i] = gh[i]; dl[i] = gl[i]; }
    }
    for (int idx = tid; idx < KCH*(PTILE/4); idx += 256) {
        const int k  = idx >> 5;
        const int p4 = idx & 31;
        const float4 v = *(const float4*)(srcs[k >> 6] + (size_t)(k & 63)*NT + p0 + p4*4);
        __nv_bfloat16 h0,l0,h1,l1,h2,l2,h3,l3;
        split_bf16(v.x, h0, l0); split_bf16(v.y, h1, l1);
        split_bf16(v.z, h2, l2); split_bf16(v.w, h3, l3);
        __nv_bfloat162 hh[2] = { {h0,h1}, {h2,h3} };
        __nv_bfloat162 ll[2] = { {l0,l1}, {l2,l3} };
        *(uint2*)(sBH + k*SC + p4*4) = *(uint2*)hh;
        *(uint2*)(sBL + k*SC + p4*4) = *(uint2*)ll;
    }
    __syncthreads();

    float acc[2][4][4];
    #pragma unroll
    for (int mi = 0; mi < 2; mi++)
        #pragma unroll
        for (int ni = 0; ni < 4; ni++)
            #pragma unroll
            for (int p = 0; p < 4; p++) acc[mi][ni][p] = 0.0f;

    const int brow_l = lane & 15;
    const int bcol_l = (lane >> 4) * 8;

    for (int k0 = 0; k0 < KCH; k0 += 16) {
        uint32_t bh[2][4], bl[2][4];
        #pragma unroll
        for (int gB = 0; gB < 2; gB++) {
            const uint32_t bb =
                (uint32_t)((k0 + brow_l)*SC + wn*32 + gB*16 + bcol_l) * 2;
            LDSM_X4T(bh[gB], cH + bb);
            LDSM_X4T(bl[gB], cL + bb);
        }
        #pragma unroll
        for (int mi = 0; mi < 2; mi++) {
            uint32_t ah[4], al[4];
            const uint32_t ab =
                (uint32_t)(((wm*2 + mi)*16 + brow_l)*SW + k0 + bcol_l) * 2;
            LDSM_X4(ah, wH + ab);
            LDSM_X4(al, wL + ab);
            #pragma unroll
            for (int gB = 0; gB < 2; gB++)
                #pragma unroll
                for (int s = 0; s < 2; s++) {
                    float* d = acc[mi][gB*2 + s];
                    MMA_BF16(d, ah, bh[gB][s*2], bh[gB][s*2+1]);
                    MMA_BF16(d, ah, bl[gB][s*2], bl[gB][s*2+1]);
                    MMA_BF16(d, al, bh[gB][s*2], bh[gB][s*2+1]);
                }
        }
    }

    const int g  = lane >> 2;
    const int c2 = (lane & 3) * 2;
    float* outb = out + (size_t)b * (COUT*(size_t)NT);
    #pragma unroll
    for (int mi = 0; mi < 2; mi++)
        #pragma unroll
        for (int rr = 0; rr < 2; rr++) {
            const int o = (wm*2 + mi)*16 + g + rr*8;
            const float bv = __ldg(bias + o);
            #pragma unroll
            for (int ni = 0; ni < 4; ni++) {
                const int pos = p0 + wn*32 + ni*8 + c2;
                float2 r;
                r.x = acc[mi][ni][rr*2]   + bv;
                r.y = acc[mi][ni][rr*2+1] + bv;
                *(float2*)(outb + (size_t)o*NT + pos) = r;
            }
        }
}

// ---------------------------------------------------------------------------
extern "C" void kernel_launch(void* const* d_in, const int* in_sizes, int n_in,
                              void* d_out, int out_size)
{
    const float* x    = (const float*)d_in[0];
    const float* adj  = (const float*)d_in[1];
    const float* W    = (const float*)d_in[2];
    const float* bias = (const float*)d_in[3];
    float* out = (float*)d_out;

    cudaFuncSetAttribute(k_node_pers, cudaFuncAttributeMaxDynamicSharedMemorySize,
                         NODE_SMEM);
    cudaFuncSetAttribute(k_chan_hmma, cudaFuncAttributeMaxDynamicSharedMemorySize,
                         CHAN_SMEM);

    k_prep_w<<<(COUT*SW + 255)/256, 256>>>(W);
    k_prep_adj<<<(MPAD*SA + 255)/256, 256>>>(adj);
    k_node_pers<<<NODE_GRID, 512, NODE_SMEM>>>(x);
    dim3 cgrid(NT/PTILE, BATCH);    // (85, 32)
    k_chan_hmma<<<cgrid, 256, CHAN_SMEM>>>(x, bias, out);
}

// round 14
// speedup vs baseline: 1.4597x; 1.0239x over previous
#include <cuda_runtime.h>
#include <cuda_bf16.h>
#include <cstdint>

#define NNODE 170
#define MPAD  176          // node dim padded to 11 m-tiles of 16
#define SA    184          // adj smem row stride (elems)
#define SB2   136          // node B tile row stride (elems), 128 cols used
#define TSEQ  64
#define CIN   64
#define COUT  64
#define BATCH 32
#define NT    (NNODE*TSEQ)          // 10880 = 85 * 128 = 170 * 64
#define BSTRIDE (CIN*NT)
#define NITEMS (BATCH*CIN)          // 2048
#define NPAIR  (NITEMS/2)           // 1024
#define NODE_GRID 148

#define KCH   192          // channel-stage K = 3*CIN
#define SW    200          // W image row stride (elems)
#define SC2   72           // chan B tile row stride (elems), 64 cols used
#define PT2   64           // pos per chan item
#define CH_ITEMS (BATCH*(NT/PT2))   // 32*170 = 5440
#define CH_GRID 296                 // 2 CTAs per SM

typedef unsigned long long u64;

// ---------------- device scratch (no allocs allowed) -----------------------
__device__ float g_Y1[BATCH*CIN*NT];
__device__ float g_Y2[BATCH*CIN*NT];
__device__ __align__(16) __nv_bfloat16 g_adjh[MPAD*SA]; // padded [176][184]
__device__ __align__(16) __nv_bfloat16 g_adjl[MPAD*SA];
__device__ __align__(16) __nv_bfloat16 g_Wh[COUT*SW];   // [o][k=s*64+c] hi
__device__ __align__(16) __nv_bfloat16 g_Wl[COUT*SW];   // lo

// ---------------- node smem map (bytes) -------------------------------------
#define AH_OFF 0                        // 176*184*2 = 64768
#define AL_OFF 64768
#define BH_OFF 129536                   // 176*136*2 = 47872
#define BL_OFF 177408
#define NODE_SMEM 225280                // <= 227 KB cap

// ---------------- chan smem map (bytes) -------------------------------------
#define WH_OFF 0                        // 64*200*2 = 25600
#define WL_OFF 25600
#define CBH_OFF 51200                   // 192*72*2 = 27648
#define CBL_OFF 78848
#define CHAN_SMEM 106496                // 2 CTAs/SM (2x106496 <= 227KB)

// ---------------- helpers ---------------------------------------------------
__device__ __forceinline__ uint32_t smem_u32(const void* p) {
    uint32_t a;
    asm("{ .reg .u64 t; cvta.to.shared.u64 t, %1; cvt.u32.u64 %0, t; }"
        : "=r"(a) : "l"(p));
    return a;
}

#define LDSM_X4(r, addr) \
    asm volatile("ldmatrix.sync.aligned.m8n8.x4.shared.b16 {%0,%1,%2,%3}, [%4];" \
        : "=r"((r)[0]), "=r"((r)[1]), "=r"((r)[2]), "=r"((r)[3]) : "r"(addr))
#define LDSM_X4T(r, addr) \
    asm volatile("ldmatrix.sync.aligned.m8n8.x4.trans.shared.b16 {%0,%1,%2,%3}, [%4];" \
        : "=r"((r)[0]), "=r"((r)[1]), "=r"((r)[2]), "=r"((r)[3]) : "r"(addr))

#define MMA_BF16(d, a, b0, b1) \
    asm volatile("mma.sync.aligned.m16n8k16.row.col.f32.bf16.bf16.f32 " \
        "{%0,%1,%2,%3}, {%4,%5,%6,%7}, {%8,%9}, {%0,%1,%2,%3};" \
        : "+f"((d)[0]), "+f"((d)[1]), "+f"((d)[2]), "+f"((d)[3]) \
        : "r"((a)[0]), "r"((a)[1]), "r"((a)[2]), "r"((a)[3]), "r"(b0), "r"(b1))

__device__ __forceinline__ void split_bf16(float v, __nv_bfloat16& h, __nv_bfloat16& l) {
    h = __float2bfloat16(v);
    l = __float2bfloat16(v - __bfloat162float(h));
}

// ---------------------------------------------------------------------------
// Prep kernels
// ---------------------------------------------------------------------------
__global__ void k_prep_w(const float* __restrict__ W)
{
    int i = blockIdx.x * 256 + threadIdx.x;     // over 64*SW
    if (i >= COUT*SW) return;
    int o = i / SW, k = i % SW;
    float v = 0.0f;
    if (k < KCH) {
        int s = k >> 6, c = k & 63;
        v = W[o*KCH + c*3 + s];
    }
    __nv_bfloat16 h, l;
    split_bf16(v, h, l);
    g_Wh[i] = h;
    g_Wl[i] = l;
}

__global__ void k_prep_adj(const float* __restrict__ adj)
{
    int i = blockIdx.x * 256 + threadIdx.x;
    if (i >= MPAD*SA) return;
    int q = i / SA, k = i % SA;
    float a = (q < NNODE && k < NNODE) ? adj[q*NNODE + k] : 0.0f;
    __nv_bfloat16 h, l;
    split_bf16(a, h, l);
    g_adjh[i] = h;
    g_adjl[i] = l;
}

// ---------------------------------------------------------------------------
// Node GEMM, 2-item wide (N=128) — unchanged from R13
// ---------------------------------------------------------------------------
__device__ __forceinline__ void gemm_n128(uint32_t aH, uint32_t aL,
                                          uint32_t bH, uint32_t bL,
                                          int w, int lane, float acc[3][4][4])
{
    #pragma unroll
    for (int u = 0; u < 3; u++)
        #pragma unroll
        for (int n = 0; n < 4; n++)
            #pragma unroll
            for (int p = 0; p < 4; p++) acc[u][n][p] = 0.0f;

    const int nq   = w & 3;
    const int mt0  = w >> 2;
    const bool hasC = (mt0 < 3);
    const int brow = lane & 15;
    const int bcol = (lane >> 4) * 8;

    for (int k0 = 0; k0 < MPAD; k0 += 16) {
        uint32_t bh[2][4], bl[2][4];
        #pragma unroll
        for (int gB = 0; gB < 2; gB++) {
            const uint32_t bb =
                (uint32_t)((k0 + brow)*SB2 + nq*32 + gB*16 + bcol) * 2;
            LDSM_X4T(bh[gB], bH + bb);
            LDSM_X4T(bl[gB], bL + bb);
        }
        #pragma unroll
        for (int u = 0; u < 3; u++) {
            if (u == 2 && !hasC) break;
            const int mt = u*4 + mt0;
            uint32_t ah[4], al[4];
            const uint32_t ab = (uint32_t)((mt*16 + brow)*SA + k0 + bcol) * 2;
            LDSM_X4(ah, aH + ab);
            LDSM_X4(al, aL + ab);
            #pragma unroll
            for (int gB = 0; gB < 2; gB++)
                #pragma unroll
                for (int s = 0; s < 2; s++) {
                    float* d = acc[u][gB*2 + s];
                    MMA_BF16(d, ah, bh[gB][s*2], bh[gB][s*2+1]);
                    MMA_BF16(d, ah, bl[gB][s*2], bl[gB][s*2+1]);
                    MMA_BF16(d, al, bh[gB][s*2], bh[gB][s*2+1]);
                }
        }
    }
}

// ---------------------------------------------------------------------------
// Persistent node stage, 2 items per iteration (unchanged from R13)
// ---------------------------------------------------------------------------
__global__ __launch_bounds__(512, 1) void k_node_pers(const float* __restrict__ x)
{
    extern __shared__ char smem[];
    const uint32_t sbase = smem_u32(smem);
    const uint32_t aH = sbase + AH_OFF, aL = sbase + AL_OFF;
    const uint32_t bHo = sbase + BH_OFF, bLo = sbase + BL_OFF;
    __nv_bfloat16* sBH = (__nv_bfloat16*)(smem + BH_OFF);
    __nv_bfloat16* sBL = (__nv_bfloat16*)(smem + BL_OFF);

    const int tid  = threadIdx.x;
    const int w    = tid >> 5;
    const int lane = tid & 31;
    const int g    = lane >> 2;
    const int c2   = (lane & 3) * 2;
    const int nq   = w & 3;
    const int mt0  = w >> 2;
    const bool hasC = (mt0 < 3);
    const int item = nq >> 1;
    const int tbase = nq*32 - item*64;

    {
        const float4* gh = (const float4*)g_adjh;
        const float4* gl = (const float4*)g_adjl;
        float4* dh = (float4*)(smem + AH_OFF);
        float4* dl = (float4*)(smem + AL_OFF);
        for (int i = tid; i < (MPAD*SA*2)/16; i += 512) { dh[i] = gh[i]; dl[i] = gl[i]; }
    }
    for (int i = tid; i < (MPAD - NNODE)*SB2; i += 512) {
        const int idx = NNODE*SB2 + i;
        sBH[idx] = __float2bfloat16(0.f);
        sBL[idx] = __float2bfloat16(0.f);
    }

    float acc[3][4][4];

    for (int it2 = blockIdx.x; it2 < NPAIR; it2 += NODE_GRID) {
        const float* Xg0 = x + (size_t)(it2*2) * NT;
        const float* Xg  = Xg0 + (size_t)item * NT;
        float* Y1g = g_Y1 + (size_t)(it2*2 + item) * NT;
        float* Y2g = g_Y2 + (size_t)(it2*2 + item) * NT;

        __syncthreads();
        for (int idx = tid; idx < NNODE*32; idx += 512) {
            const int n   = idx >> 5;
            const int c4  = idx & 31;
            const int itm = c4 >> 4;
            const int t4  = c4 & 15;
            const float4 v = __ldg((const float4*)(Xg0 + (size_t)itm*NT + n*TSEQ) + t4);
            __nv_bfloat16 h0,l0,h1,l1,h2,l2,h3,l3;
            split_bf16(v.x, h0, l0); split_bf16(v.y, h1, l1);
            split_bf16(v.z, h2, l2); split_bf16(v.w, h3, l3);
            __nv_bfloat162 hh[2] = { {h0,h1}, {h2,h3} };
            __nv_bfloat162 ll[2] = { {l0,l1}, {l2,l3} };
            *(uint2*)(sBH + n*SB2 + c4*4) = *(uint2*)hh;
            *(uint2*)(sBL + n*SB2 + c4*4) = *(uint2*)ll;
        }
        __syncthreads();

        gemm_n128(aH, aL, bHo, bLo, w, lane, acc);
        __syncthreads();

        #pragma unroll
        for (int u = 0; u < 3; u++) {
            if (u == 2 && !hasC) break;
            const int mt = u*4 + mt0;
            #pragma unroll
            for (int nt = 0; nt < 4; nt++) {
                const int col = nq*32 + nt*8 + c2;
                const int t   = tbase + nt*8 + c2;
                #pragma unroll
                for (int rr = 0; rr < 2; rr++) {
                    const int q = mt*16 + g + rr*8;
                    const float v0 = acc[u][nt][rr*2];
                    const float v1 = acc[u][nt][rr*2+1];
                    if (q < NNODE) {
                        float2 o; o.x = v0; o.y = v1;
                        *(float2*)(Y1g + q*TSEQ + t) = o;
                    }
                    __nv_bfloat162 h2, l2;
                    split_bf16(v0, h2.x, l2.x);
                    split_bf16(v1, h2.y, l2.y);
                    *(__nv_bfloat162*)(sBH + q*SB2 + col) = h2;
                    *(__nv_bfloat162*)(sBL + q*SB2 + col) = l2;
                }
            }
        }
        __syncthreads();

        gemm_n128(aH, aL, bHo, bLo, w, lane, acc);

        #pragma unroll
        for (int u = 0; u < 3; u++) {
            if (u == 2 && !hasC) break;
            const int mt = u*4 + mt0;
            #pragma unroll
            for (int nt = 0; nt < 4; nt++) {
                const int t = tbase + nt*8 + c2;
                #pragma unroll
                for (int rr = 0; rr < 2; rr++) {
                    const int q = mt*16 + g + rr*8;
                    if (q < NNODE) {
                        const float2 xv = *(const float2*)(Xg + q*TSEQ + t);
                        float2 o;
                        o.x = 2.f*acc[u][nt][rr*2]   - xv.x;
                        o.y = 2.f*acc[u][nt][rr*2+1] - xv.y;
                        *(float2*)(Y2g + q*TSEQ + t) = o;
                    }
                }
            }
        }
    }
}

// ---------------------------------------------------------------------------
// Persistent channel stage: 128 threads (4 warps = 2m-groups x 2n), 2 CTAs/SM.
// Warp owns 2 m16-tiles x 32 pos (MMA/ldsm ratio 3.0, same as R8).
// W staged once per CTA; loop over (b, 64-pos tile) items.
// ---------------------------------------------------------------------------
__global__ __launch_bounds__(128, 2) void k_chan_pers(const float* __restrict__ x,
                                                      const float* __restrict__ bias,
                                                      float* __restrict__ out)
{
    extern __shared__ char smem[];
    const uint32_t sbase = smem_u32(smem);
    const uint32_t wH = sbase + WH_OFF, wL = sbase + WL_OFF;
    const uint32_t cH = sbase + CBH_OFF, cL = sbase + CBL_OFF;
    __nv_bfloat16* sBH = (__nv_bfloat16*)(smem + CBH_OFF);
    __nv_bfloat16* sBL = (__nv_bfloat16*)(smem + CBL_OFF);

    const int tid  = threadIdx.x;
    const int w    = tid >> 5;
    const int lane = tid & 31;
    const int wm   = w & 1;          // m half: o 0-31 / 32-63 (2 tiles each)
    const int wn   = w >> 1;         // n half: 32 pos each
    const int g    = lane >> 2;
    const int c2   = (lane & 3) * 2;
    const int brow_l = lane & 15;
    const int bcol_l = (lane >> 4) * 8;

    // ---- stage W hi/lo once per CTA ----
    {
        const float4* gh = (const float4*)g_Wh;
        const float4* gl = (const float4*)g_Wl;
        float4* dh = (float4*)(smem + WH_OFF);
        float4* dl = (float4*)(smem + WL_OFF);
        for (int i = tid; i < (COUT*SW*2)/16; i += 128) { dh[i] = gh[i]; dl[i] = gl[i]; }
    }

    for (int it = blockIdx.x; it < CH_ITEMS; it += CH_GRID) {
        const int b  = it / (NT/PT2);
        const int p0 = (it % (NT/PT2)) * PT2;

        const float* srcs[3];
        srcs[0] = x    + (size_t)b * BSTRIDE;
        srcs[1] = g_Y1 + (size_t)b * BSTRIDE;
        srcs[2] = g_Y2 + (size_t)b * BSTRIDE;

        __syncthreads();   // prior GEMM readers done before B overwrite
        // ---- stage B tile [192][64] f32 -> bf16 hi/lo ----
        for (int idx = tid; idx < KCH*(PT2/4); idx += 128) {   // 3072 float4
            const int k  = idx >> 4;          // 0..191
            const int p4 = idx & 15;
            const float4 v = *(const float4*)(srcs[k >> 6] + (size_t)(k & 63)*NT + p0 + p4*4);
            __nv_bfloat16 h0,l0,h1,l1,h2,l2,h3,l3;
            split_bf16(v.x, h0, l0); split_bf16(v.y, h1, l1);
            split_bf16(v.z, h2, l2); split_bf16(v.w, h3, l3);
            __nv_bfloat162 hh[2] = { {h0,h1}, {h2,h3} };
            __nv_bfloat162 ll[2] = { {l0,l1}, {l2,l3} };
            *(uint2*)(sBH + k*SC2 + p4*4) = *(uint2*)hh;
            *(uint2*)(sBL + k*SC2 + p4*4) = *(uint2*)ll;
        }
        __syncthreads();

        // ---- GEMM: M=64, N=64, K=192, 3 split passes ----
        float acc[2][4][4];
        #pragma unroll
        for (int mi = 0; mi < 2; mi++)
            #pragma unroll
            for (int ni = 0; ni < 4; ni++)
                #pragma unroll
                for (int p = 0; p < 4; p++) acc[mi][ni][p] = 0.0f;

        for (int k0 = 0; k0 < KCH; k0 += 16) {
            uint32_t bh[2][4], bl[2][4];
            #pragma unroll
            for (int gB = 0; gB < 2; gB++) {
                const uint32_t bb =
                    (uint32_t)((k0 + brow_l)*SC2 + wn*32 + gB*16 + bcol_l) * 2;
                LDSM_X4T(bh[gB], cH + bb);
                LDSM_X4T(bl[gB], cL + bb);
            }
            #pragma unroll
            for (int mi = 0; mi < 2; mi++) {
                uint32_t ah[4], al[4];
                const uint32_t ab =
                    (uint32_t)(((wm*2 + mi)*16 + brow_l)*SW + k0 + bcol_l) * 2;
                LDSM_X4(ah, wH + ab);
                LDSM_X4(al, wL + ab);
                #pragma unroll
                for (int gB = 0; gB < 2; gB++)
                    #pragma unroll
                    for (int s = 0; s < 2; s++) {
                        float* d = acc[mi][gB*2 + s];
                        MMA_BF16(d, ah, bh[gB][s*2], bh[gB][s*2+1]);
                        MMA_BF16(d, ah, bl[gB][s*2], bl[gB][s*2+1]);
                        MMA_BF16(d, al, bh[gB][s*2], bh[gB][s*2+1]);
                    }
            }
        }

        // ---- epilogue: bias + store ----
        float* outb = out + (size_t)b * (COUT*(size_t)NT);
        #pragma unroll
        for (int mi = 0; mi < 2; mi++)
            #pragma unroll
            for (int rr = 0; rr < 2; rr++) {
                const int o = (wm*2 + mi)*16 + g + rr*8;
                const float bv = __ldg(bias + o);
                #pragma unroll
                for (int ni = 0; ni < 4; ni++) {
                    const int pos = p0 + wn*32 + ni*8 + c2;
                    float2 r;
                    r.x = acc[mi][ni][rr*2]   + bv;
                    r.y = acc[mi][ni][rr*2+1] + bv;
                    *(float2*)(outb + (size_t)o*NT + pos) = r;
                }
            }
    }
}

// ---------------------------------------------------------------------------
extern "C" void kernel_launch(void* const* d_in, const int* in_sizes, int n_in,
                              void* d_out, int out_size)
{
    const float* x    = (const float*)d_in[0];
    const float* adj  = (const float*)d_in[1];
    const float* W    = (const float*)d_in[2];
    const float* bias = (const float*)d_in[3];
    float* out = (float*)d_out;

    cudaFuncSetAttribute(k_node_pers, cudaFuncAttributeMaxDynamicSharedMemorySize,
                         NODE_SMEM);
    cudaFuncSetAttribute(k_chan_pers, cudaFuncAttributeMaxDynamicSharedMemorySize,
                         CHAN_SMEM);

    k_prep_w<<<(COUT*SW + 255)/256, 256>>>(W);
    k_prep_adj<<<(MPAD*SA + 255)/256, 256>>>(adj);
    k_node_pers<<<NODE_GRID, 512, NODE_SMEM>>>(x);
    k_chan_pers<<<CH_GRID, 128, CHAN_SMEM>>>(x, bias, out);
}

// round 15
// speedup vs baseline: 1.9041x; 1.3045x over previous
#include <cuda_runtime.h>
#include <cuda_fp16.h>
#include <cstdint>

#define NNODE 170
#define MPAD  176          // node dim padded to 11 m-tiles of 16
#define SA    184          // adj smem row stride (elems)
#define SB2   136          // node B tile row stride (elems), 128 cols used
#define TSEQ  64
#define CIN   64
#define COUT  64
#define BATCH 32
#define NT    (NNODE*TSEQ)          // 10880 = 85 * 128 = 170 * 64
#define BSTRIDE (CIN*NT)
#define NITEMS (BATCH*CIN)          // 2048
#define NPAIR  (NITEMS/2)           // 1024
#define NODE_GRID 148

#define KCH   192          // channel-stage K = 3*CIN
#define SW    200          // W image row stride (elems)
#define SC2   72           // chan B tile row stride (elems), 64 cols used
#define PT2   64           // pos per chan item
#define CH_ITEMS (BATCH*(NT/PT2))   // 32*170 = 5440
#define CH_GRID 296                 // 2 CTAs per SM

typedef unsigned long long u64;

// ---------------- device scratch (no allocs allowed) -----------------------
__device__ float g_Y1[BATCH*CIN*NT];
__device__ float g_Y2[BATCH*CIN*NT];
__device__ __align__(16) __half g_adjh[MPAD*SA]; // padded [176][184], fp16 hi only
__device__ __align__(16) __half g_Wh[COUT*SW];   // [o][k=s*64+c] fp16 hi only

// ---------------- node smem map (bytes) -------------------------------------
#define AH_OFF 0                        // 176*184*2 = 64768
#define BH_OFF 64768                    // 176*136*2 = 47872
#define BL_OFF 112640
#define NODE_SMEM 160512

// ---------------- chan smem map (bytes) -------------------------------------
#define WH_OFF 0                        // 64*200*2 = 25600
#define CBH_OFF 25600                   // 192*72*2 = 27648
#define CBL_OFF 53248
#define CHAN_SMEM 80896                 // 2 CTAs/SM

// ---------------- helpers ---------------------------------------------------
__device__ __forceinline__ uint32_t smem_u32(const void* p) {
    uint32_t a;
    asm("{ .reg .u64 t; cvta.to.shared.u64 t, %1; cvt.u32.u64 %0, t; }"
        : "=r"(a) : "l"(p));
    return a;
}

#define LDSM_X4(r, addr) \
    asm volatile("ldmatrix.sync.aligned.m8n8.x4.shared.b16 {%0,%1,%2,%3}, [%4];" \
        : "=r"((r)[0]), "=r"((r)[1]), "=r"((r)[2]), "=r"((r)[3]) : "r"(addr))
#define LDSM_X4T(r, addr) \
    asm volatile("ldmatrix.sync.aligned.m8n8.x4.trans.shared.b16 {%0,%1,%2,%3}, [%4];" \
        : "=r"((r)[0]), "=r"((r)[1]), "=r"((r)[2]), "=r"((r)[3]) : "r"(addr))

#define MMA_F16(d, a, b0, b1) \
    asm volatile("mma.sync.aligned.m16n8k16.row.col.f32.f16.f16.f32 " \
        "{%0,%1,%2,%3}, {%4,%5,%6,%7}, {%8,%9}, {%0,%1,%2,%3};" \
        : "+f"((d)[0]), "+f"((d)[1]), "+f"((d)[2]), "+f"((d)[3]) \
        : "r"((a)[0]), "r"((a)[1]), "r"((a)[2]), "r"((a)[3]), "r"(b0), "r"(b1))

__device__ __forceinline__ void split_f16(float v, __half& h, __half& l) {
    h = __float2half_rn(v);
    l = __float2half_rn(v - __half2float(h));
}

// ---------------------------------------------------------------------------
// Prep kernels
// ---------------------------------------------------------------------------
__global__ void k_prep_w(const float* __restrict__ W)
{
    int i = blockIdx.x * 256 + threadIdx.x;     // over 64*SW
    if (i >= COUT*SW) return;
    int o = i / SW, k = i % SW;
    float v = 0.0f;
    if (k < KCH) {
        int s = k >> 6, c = k & 63;
        v = W[o*KCH + c*3 + s];
    }
    g_Wh[i] = __float2half_rn(v);
}

__global__ void k_prep_adj(const float* __restrict__ adj)
{
    int i = blockIdx.x * 256 + threadIdx.x;
    if (i >= MPAD*SA) return;
    int q = i / SA, k = i % SA;
    float a = (q < NNODE && k < NNODE) ? adj[q*NNODE + k] : 0.0f;
    g_adjh[i] = __float2half_rn(a);
}

// ---------------------------------------------------------------------------
// Node GEMM, 2-item wide (N=128), fp16 2-pass: acc = Ah@(Bh + Bl)
// 16 warps, warp w owns n-chunk (w&3)*32 and m-tiles {w>>2, 4+(w>>2),
// 8+(w>>2) if <11}.
// ---------------------------------------------------------------------------
__device__ __forceinline__ void gemm_n128(uint32_t aH,
                                          uint32_t bH, uint32_t bL,
                                          int w, int lane, float acc[3][4][4])
{
    #pragma unroll
    for (int u = 0; u < 3; u++)
        #pragma unroll
        for (int n = 0; n < 4; n++)
            #pragma unroll
            for (int p = 0; p < 4; p++) acc[u][n][p] = 0.0f;

    const int nq   = w & 3;
    const int mt0  = w >> 2;
    const bool hasC = (mt0 < 3);
    const int brow = lane & 15;
    const int bcol = (lane >> 4) * 8;

    for (int k0 = 0; k0 < MPAD; k0 += 16) {
        uint32_t bh[2][4], bl[2][4];
        #pragma unroll
        for (int gB = 0; gB < 2; gB++) {
            const uint32_t bb =
                (uint32_t)((k0 + brow)*SB2 + nq*32 + gB*16 + bcol) * 2;
            LDSM_X4T(bh[gB], bH + bb);
            LDSM_X4T(bl[gB], bL + bb);
        }
        #pragma unroll
        for (int u = 0; u < 3; u++) {
            if (u == 2 && !hasC) break;
            const int mt = u*4 + mt0;
            uint32_t ah[4];
            const uint32_t ab = (uint32_t)((mt*16 + brow)*SA + k0 + bcol) * 2;
            LDSM_X4(ah, aH + ab);
            #pragma unroll
            for (int gB = 0; gB < 2; gB++)
                #pragma unroll
                for (int s = 0; s < 2; s++) {
                    float* d = acc[u][gB*2 + s];
                    MMA_F16(d, ah, bh[gB][s*2], bh[gB][s*2+1]);
                    MMA_F16(d, ah, bl[gB][s*2], bl[gB][s*2+1]);
                }
        }
    }
}

// ---------------------------------------------------------------------------
// Persistent node stage, 2 items per iteration
// ---------------------------------------------------------------------------
__global__ __launch_bounds__(512, 1) void k_node_pers(const float* __restrict__ x)
{
    extern __shared__ char smem[];
    const uint32_t sbase = smem_u32(smem);
    const uint32_t aH = sbase + AH_OFF;
    const uint32_t bHo = sbase + BH_OFF, bLo = sbase + BL_OFF;
    __half* sBH = (__half*)(smem + BH_OFF);
    __half* sBL = (__half*)(smem + BL_OFF);

    const int tid  = threadIdx.x;
    const int w    = tid >> 5;
    const int lane = tid & 31;
    const int g    = lane >> 2;
    const int c2   = (lane & 3) * 2;
    const int nq   = w & 3;
    const int mt0  = w >> 2;
    const bool hasC = (mt0 < 3);
    const int item = nq >> 1;
    const int tbase = nq*32 - item*64;

    // ---- stage adj hi once ----
    {
        const float4* gh = (const float4*)g_adjh;
        float4* dh = (float4*)(smem + AH_OFF);
        for (int i = tid; i < (MPAD*SA*2)/16; i += 512) dh[i] = gh[i];
    }
    // zero B pad rows once
    for (int i = tid; i < (MPAD - NNODE)*SB2; i += 512) {
        const int idx = NNODE*SB2 + i;
        sBH[idx] = __float2half_rn(0.f);
        sBL[idx] = __float2half_rn(0.f);
    }

    float acc[3][4][4];

    for (int it2 = blockIdx.x; it2 < NPAIR; it2 += NODE_GRID) {
        const float* Xg0 = x + (size_t)(it2*2) * NT;
        const float* Xg  = Xg0 + (size_t)item * NT;
        float* Y1g = g_Y1 + (size_t)(it2*2 + item) * NT;
        float* Y2g = g_Y2 + (size_t)(it2*2 + item) * NT;

        __syncthreads();
        // ---- stage X of both items: B[n][col], col = itm*64 + t ----
        for (int idx = tid; idx < NNODE*32; idx += 512) {
            const int n   = idx >> 5;
            const int c4  = idx & 31;
            const int itm = c4 >> 4;
            const int t4  = c4 & 15;
            const float4 v = __ldg((const float4*)(Xg0 + (size_t)itm*NT + n*TSEQ) + t4);
            __half h0,l0,h1,l1,h2,l2,h3,l3;
            split_f16(v.x, h0, l0); split_f16(v.y, h1, l1);
            split_f16(v.z, h2, l2); split_f16(v.w, h3, l3);
            __half2 hh[2] = { {h0,h1}, {h2,h3} };
            __half2 ll[2] = { {l0,l1}, {l2,l3} };
            *(uint2*)(sBH + n*SB2 + c4*4) = *(uint2*)hh;
            *(uint2*)(sBL + n*SB2 + c4*4) = *(uint2*)ll;
        }
        __syncthreads();

        // ======== GEMM 1: Y1 = adj @ [X0|X1] ========
        gemm_n128(aH, bHo, bLo, w, lane, acc);
        __syncthreads();

        // epilogue 1: write Y1 f32 + resplit into B
        #pragma unroll
        for (int u = 0; u < 3; u++) {
            if (u == 2 && !hasC) break;
            const int mt = u*4 + mt0;
            #pragma unroll
            for (int nt = 0; nt < 4; nt++) {
                const int col = nq*32 + nt*8 + c2;
                const int t   = tbase + nt*8 + c2;
                #pragma unroll
                for (int rr = 0; rr < 2; rr++) {
                    const int q = mt*16 + g + rr*8;
                    const float v0 = acc[u][nt][rr*2];
                    const float v1 = acc[u][nt][rr*2+1];
                    if (q < NNODE) {
                        float2 o; o.x = v0; o.y = v1;
                        *(float2*)(Y1g + q*TSEQ + t) = o;
                    }
                    __half2 h2, l2;
                    split_f16(v0, h2.x, l2.x);
                    split_f16(v1, h2.y, l2.y);
                    *(__half2*)(sBH + q*SB2 + col) = h2;
                    *(__half2*)(sBL + q*SB2 + col) = l2;
                }
            }
        }
        __syncthreads();

        // ======== GEMM 2: Y2 = 2*adj @ Y1 - X ========
        gemm_n128(aH, bHo, bLo, w, lane, acc);

        #pragma unroll
        for (int u = 0; u < 3; u++) {
            if (u == 2 && !hasC) break;
            const int mt = u*4 + mt0;
            #pragma unroll
            for (int nt = 0; nt < 4; nt++) {
                const int t = tbase + nt*8 + c2;
                #pragma unroll
                for (int rr = 0; rr < 2; rr++) {
                    const int q = mt*16 + g + rr*8;
                    if (q < NNODE) {
                        const float2 xv = *(const float2*)(Xg + q*TSEQ + t);
                        float2 o;
                        o.x = 2.f*acc[u][nt][rr*2]   - xv.x;
                        o.y = 2.f*acc[u][nt][rr*2+1] - xv.y;
                        *(float2*)(Y2g + q*TSEQ + t) = o;
                    }
                }
            }
        }
    }
}

// ---------------------------------------------------------------------------
// Persistent channel stage: 128 threads (4 warps = 2m-groups x 2n), 2 CTAs/SM.
// fp16 2-pass: out = Wh @ (Bh + Bl) + bias
// ---------------------------------------------------------------------------
__global__ __launch_bounds__(128, 2) void k_chan_pers(const float* __restrict__ x,
                                                      const float* __restrict__ bias,
                                                      float* __restrict__ out)
{
    extern __shared__ char smem[];
    const uint32_t sbase = smem_u32(smem);
    const uint32_t wH = sbase + WH_OFF;
    const uint32_t cH = sbase + CBH_OFF, cL = sbase + CBL_OFF;
    __half* sBH = (__half*)(smem + CBH_OFF);
    __half* sBL = (__half*)(smem + CBL_OFF);

    const int tid  = threadIdx.x;
    const int w    = tid >> 5;
    const int lane = tid & 31;
    const int wm   = w & 1;          // m half: o 0-31 / 32-63 (2 tiles each)
    const int wn   = w >> 1;         // n half: 32 pos each
    const int g    = lane >> 2;
    const int c2   = (lane & 3) * 2;
    const int brow_l = lane & 15;
    const int bcol_l = (lane >> 4) * 8;

    // ---- stage W hi once per CTA ----
    {
        const float4* gh = (const float4*)g_Wh;
        float4* dh = (float4*)(smem + WH_OFF);
        for (int i = tid; i < (COUT*SW*2)/16; i += 128) dh[i] = gh[i];
    }

    for (int it = blockIdx.x; it < CH_ITEMS; it += CH_GRID) {
        const int b  = it / (NT/PT2);
        const int p0 = (it % (NT/PT2)) * PT2;

        const float* srcs[3];
        srcs[0] = x    + (size_t)b * BSTRIDE;
        srcs[1] = g_Y1 + (size_t)b * BSTRIDE;
        srcs[2] = g_Y2 + (size_t)b * BSTRIDE;

        __syncthreads();
        // ---- stage B tile [192][64] f32 -> fp16 hi/lo ----
        for (int idx = tid; idx < KCH*(PT2/4); idx += 128) {
            const int k  = idx >> 4;
            const int p4 = idx & 15;
            const float4 v = *(const float4*)(srcs[k >> 6] + (size_t)(k & 63)*NT + p0 + p4*4);
            __half h0,l0,h1,l1,h2,l2,h3,l3;
            split_f16(v.x, h0, l0); split_f16(v.y, h1, l1);
            split_f16(v.z, h2, l2); split_f16(v.w, h3, l3);
            __half2 hh[2] = { {h0,h1}, {h2,h3} };
            __half2 ll[2] = { {l0,l1}, {l2,l3} };
            *(uint2*)(sBH + k*SC2 + p4*4) = *(uint2*)hh;
            *(uint2*)(sBL + k*SC2 + p4*4) = *(uint2*)ll;
        }
        __syncthreads();

        // ---- GEMM: M=64, N=64, K=192, 2 passes ----
        float acc[2][4][4];
        #pragma unroll
        for (int mi = 0; mi < 2; mi++)
            #pragma unroll
            for (int ni = 0; ni < 4; ni++)
                #pragma unroll
                for (int p = 0; p < 4; p++) acc[mi][ni][p] = 0.0f;

        for (int k0 = 0; k0 < KCH; k0 += 16) {
            uint32_t bh[2][4], bl[2][4];
            #pragma unroll
            for (int gB = 0; gB < 2; gB++) {
                const uint32_t bb =
                    (uint32_t)((k0 + brow_l)*SC2 + wn*32 + gB*16 + bcol_l) * 2;
                LDSM_X4T(bh[gB], cH + bb);
                LDSM_X4T(bl[gB], cL + bb);
            }
            #pragma unroll
            for (int mi = 0; mi < 2; mi++) {
                uint32_t ah[4];
                const uint32_t ab =
                    (uint32_t)(((wm*2 + mi)*16 + brow_l)*SW + k0 + bcol_l) * 2;
                LDSM_X4(ah, wH + ab);
                #pragma unroll
                for (int gB = 0; gB < 2; gB++)
                    #pragma unroll
                    for (int s = 0; s < 2; s++) {
                        float* d = acc[mi][gB*2 + s];
                        MMA_F16(d, ah, bh[gB][s*2], bh[gB][s*2+1]);
                        MMA_F16(d, ah, bl[gB][s*2], bl[gB][s*2+1]);
                    }
            }
        }

        // ---- epilogue: bias + store ----
        float* outb = out + (size_t)b * (COUT*(size_t)NT);
        #pragma unroll
        for (int mi = 0; mi < 2; mi++)
            #pragma unroll
            for (int rr = 0; rr < 2; rr++) {
                const int o = (wm*2 + mi)*16 + g + rr*8;
                const float bv = __ldg(bias + o);
                #pragma unroll
                for (int ni = 0; ni < 4; ni++) {
                    const int pos = p0 + wn*32 + ni*8 + c2;
                    float2 r;
                    r.x = acc[mi][ni][rr*2]   + bv;
                    r.y = acc[mi][ni][rr*2+1] + bv;
                    *(float2*)(outb + (size_t)o*NT + pos) = r;
                }
            }
    }
}

// ---------------------------------------------------------------------------
extern "C" void kernel_launch(void* const* d_in, const int* in_sizes, int n_in,
                              void* d_out, int out_size)
{
    const float* x    = (const float*)d_in[0];
    const float* adj  = (const float*)d_in[1];
    const float* W    = (const float*)d_in[2];
    const float* bias = (const float*)d_in[3];
    float* out = (float*)d_out;

    cudaFuncSetAttribute(k_node_pers, cudaFuncAttributeMaxDynamicSharedMemorySize,
                         NODE_SMEM);
    cudaFuncSetAttribute(k_chan_pers, cudaFuncAttributeMaxDynamicSharedMemorySize,
                         CHAN_SMEM);

    k_prep_w<<<(COUT*SW + 255)/256, 256>>>(W);
    k_prep_adj<<<(MPAD*SA + 255)/256, 256>>>(adj);
    k_node_pers<<<NODE_GRID, 512, NODE_SMEM>>>(x);
    k_chan_pers<<<CH_GRID, 128, CHAN_SMEM>>>(x, bias, out);
}

// round 16
// speedup vs baseline: 1.9996x; 1.0502x over previous
#include <cuda_runtime.h>
#include <cuda_fp16.h>
#include <cstdint>

#define NNODE 170
#define MPAD  176          // node dim padded to 11 m-tiles of 16
#define SA    184          // adj smem row stride (elems)
#define SB2   136          // node B tile row stride (elems), 128 cols used
#define TSEQ  64
#define CIN   64
#define COUT  64
#define BATCH 32
#define NT    (NNODE*TSEQ)          // 10880 = 85 * 128 = 170 * 64
#define BSTRIDE (CIN*NT)
#define NITEMS (BATCH*CIN)          // 2048
#define NPAIR  (NITEMS/2)           // 1024
#define NODE_GRID 148

#define KC3   256          // chan K: [Xhi;Xlo;Y1;Z] = 4*64
#define SW3   264          // W3 image row stride (elems)
#define SC2   72           // chan B tile row stride (elems), 64 cols used
#define PT2   64           // pos per chan item
#define CH_ITEMS (BATCH*(NT/PT2))   // 32*170 = 5440
#define CH_GRID 296                 // 2 CTAs per SM

typedef unsigned long long u64;

// ---------------- device scratch (no allocs allowed) -----------------------
__device__ __half g_Y1h[NITEMS*NT];              // fp16 Y1  (44.6 MB)
__device__ __half g_Zh [NITEMS*NT];              // fp16 Z = adj@Y1
__device__ __align__(16) __half g_adjh[MPAD*SA]; // padded [176][184]
__device__ __align__(16) __half g_W3h[COUT*SW3]; // [o][k]: [Wx|Wx|Wy|2*W3]

// ---------------- node smem map (bytes) -------------------------------------
#define AH_OFF 0                        // 176*184*2 = 64768
#define BH_OFF 64768                    // 176*136*2 = 47872
#define BL_OFF 112640
#define NODE_SMEM 160512

// ---------------- chan smem map (bytes) -------------------------------------
#define WH_OFF 0                        // 64*264*2 = 33792
#define CB_OFF 33792                    // 256*72*2 = 36864
#define CHAN_SMEM 70656                 // 2 CTAs/SM

// ---------------- helpers ---------------------------------------------------
__device__ __forceinline__ uint32_t smem_u32(const void* p) {
    uint32_t a;
    asm("{ .reg .u64 t; cvta.to.shared.u64 t, %1; cvt.u32.u64 %0, t; }"
        : "=r"(a) : "l"(p));
    return a;
}

#define LDSM_X4(r, addr) \
    asm volatile("ldmatrix.sync.aligned.m8n8.x4.shared.b16 {%0,%1,%2,%3}, [%4];" \
        : "=r"((r)[0]), "=r"((r)[1]), "=r"((r)[2]), "=r"((r)[3]) : "r"(addr))
#define LDSM_X4T(r, addr) \
    asm volatile("ldmatrix.sync.aligned.m8n8.x4.trans.shared.b16 {%0,%1,%2,%3}, [%4];" \
        : "=r"((r)[0]), "=r"((r)[1]), "=r"((r)[2]), "=r"((r)[3]) : "r"(addr))

#define MMA_F16(d, a, b0, b1) \
    asm volatile("mma.sync.aligned.m16n8k16.row.col.f32.f16.f16.f32 " \
        "{%0,%1,%2,%3}, {%4,%5,%6,%7}, {%8,%9}, {%0,%1,%2,%3};" \
        : "+f"((d)[0]), "+f"((d)[1]), "+f"((d)[2]), "+f"((d)[3]) \
        : "r"((a)[0]), "r"((a)[1]), "r"((a)[2]), "r"((a)[3]), "r"(b0), "r"(b1))

__device__ __forceinline__ void split_f16(float v, __half& h, __half& l) {
    h = __float2half_rn(v);
    l = __float2half_rn(v - __half2float(h));
}

// ---------------------------------------------------------------------------
// Prep kernels
// ---------------------------------------------------------------------------
__global__ void k_prep_w3(const float* __restrict__ W)
{
    int i = blockIdx.x * 256 + threadIdx.x;     // over 64*SW3
    if (i >= COUT*SW3) return;
    int o = i / SW3, k = i % SW3;
    float v = 0.0f;
    if (k < 128) {          // Wx = W1 - W3 (duplicated for Xhi and Xlo)
        int c = k & 63;
        v = W[o*192 + c*3 + 0] - W[o*192 + c*3 + 2];
    } else if (k < 192) {   // Wy = W2
        int c = k - 128;
        v = W[o*192 + c*3 + 1];
    } else if (k < KC3) {   // 2*W3
        int c = k - 192;
        v = 2.0f * W[o*192 + c*3 + 2];
    }
    g_W3h[i] = __float2half_rn(v);
}

__global__ void k_prep_adj(const float* __restrict__ adj)
{
    int i = blockIdx.x * 256 + threadIdx.x;
    if (i >= MPAD*SA) return;
    int q = i / SA, k = i % SA;
    float a = (q < NNODE && k < NNODE) ? adj[q*NNODE + k] : 0.0f;
    g_adjh[i] = __float2half_rn(a);
}

// ---------------------------------------------------------------------------
// Node GEMM, 2-item wide (N=128), fp16 2-pass: acc = Ah@(Bh + Bl)
// ---------------------------------------------------------------------------
__device__ __forceinline__ void gemm_n128(uint32_t aH,
                                          uint32_t bH, uint32_t bL,
                                          int w, int lane, float acc[3][4][4])
{
    #pragma unroll
    for (int u = 0; u < 3; u++)
        #pragma unroll
        for (int n = 0; n < 4; n++)
            #pragma unroll
            for (int p = 0; p < 4; p++) acc[u][n][p] = 0.0f;

    const int nq   = w & 3;
    const int mt0  = w >> 2;
    const bool hasC = (mt0 < 3);
    const int brow = lane & 15;
    const int bcol = (lane >> 4) * 8;

    for (int k0 = 0; k0 < MPAD; k0 += 16) {
        uint32_t bh[2][4], bl[2][4];
        #pragma unroll
        for (int gB = 0; gB < 2; gB++) {
            const uint32_t bb =
                (uint32_t)((k0 + brow)*SB2 + nq*32 + gB*16 + bcol) * 2;
            LDSM_X4T(bh[gB], bH + bb);
            LDSM_X4T(bl[gB], bL + bb);
        }
        #pragma unroll
        for (int u = 0; u < 3; u++) {
            if (u == 2 && !hasC) break;
            const int mt = u*4 + mt0;
            uint32_t ah[4];
            const uint32_t ab = (uint32_t)((mt*16 + brow)*SA + k0 + bcol) * 2;
            LDSM_X4(ah, aH + ab);
            #pragma unroll
            for (int gB = 0; gB < 2; gB++)
                #pragma unroll
                for (int s = 0; s < 2; s++) {
                    float* d = acc[u][gB*2 + s];
                    MMA_F16(d, ah, bh[gB][s*2], bh[gB][s*2+1]);
                    MMA_F16(d, ah, bl[gB][s*2], bl[gB][s*2+1]);
                }
        }
    }
}

// ---------------------------------------------------------------------------
// Persistent node stage, 2 items per iteration.
//   Y1 = adj @ [X0|X1] -> fp16 gmem;  Z = adj @ Y1 -> fp16 gmem
// ---------------------------------------------------------------------------
__global__ __launch_bounds__(512, 1) void k_node_pers(const float* __restrict__ x)
{
    extern __shared__ char smem[];
    const uint32_t sbase = smem_u32(smem);
    const uint32_t aH = sbase + AH_OFF;
    const uint32_t bHo = sbase + BH_OFF, bLo = sbase + BL_OFF;
    __half* sBH = (__half*)(smem + BH_OFF);
    __half* sBL = (__half*)(smem + BL_OFF);

    const int tid  = threadIdx.x;
    const int w    = tid >> 5;
    const int lane = tid & 31;
    const int g    = lane >> 2;
    const int c2   = (lane & 3) * 2;
    const int nq   = w & 3;
    const int mt0  = w >> 2;
    const bool hasC = (mt0 < 3);
    const int item = nq >> 1;
    const int tbase = nq*32 - item*64;

    // ---- stage adj hi once ----
    {
        const float4* gh = (const float4*)g_adjh;
        float4* dh = (float4*)(smem + AH_OFF);
        for (int i = tid; i < (MPAD*SA*2)/16; i += 512) dh[i] = gh[i];
    }
    // zero B pad rows once
    for (int i = tid; i < (MPAD - NNODE)*SB2; i += 512) {
        const int idx = NNODE*SB2 + i;
        sBH[idx] = __float2half_rn(0.f);
        sBL[idx] = __float2half_rn(0.f);
    }

    float acc[3][4][4];

    for (int it2 = blockIdx.x; it2 < NPAIR; it2 += NODE_GRID) {
        const float* Xg0 = x + (size_t)(it2*2) * NT;
        __half* Y1g = g_Y1h + (size_t)(it2*2 + item) * NT;
        __half* Zg  = g_Zh  + (size_t)(it2*2 + item) * NT;

        __syncthreads();
        // ---- stage X of both items: B[n][col], col = itm*64 + t ----
        for (int idx = tid; idx < NNODE*32; idx += 512) {
            const int n   = idx >> 5;
            const int c4  = idx & 31;
            const int itm = c4 >> 4;
            const int t4  = c4 & 15;
            const float4 v = __ldg((const float4*)(Xg0 + (size_t)itm*NT + n*TSEQ) + t4);
            __half h0,l0,h1,l1,h2,l2,h3,l3;
            split_f16(v.x, h0, l0); split_f16(v.y, h1, l1);
            split_f16(v.z, h2, l2); split_f16(v.w, h3, l3);
            __half2 hh[2] = { {h0,h1}, {h2,h3} };
            __half2 ll[2] = { {l0,l1}, {l2,l3} };
            *(uint2*)(sBH + n*SB2 + c4*4) = *(uint2*)hh;
            *(uint2*)(sBL + n*SB2 + c4*4) = *(uint2*)ll;
        }
        __syncthreads();

        // ======== GEMM 1: Y1 = adj @ [X0|X1] ========
        gemm_n128(aH, bHo, bLo, w, lane, acc);
        __syncthreads();

        // epilogue 1: write Y1 fp16 gmem + resplit hi/lo into B
        #pragma unroll
        for (int u = 0; u < 3; u++) {
            if (u == 2 && !hasC) break;
            const int mt = u*4 + mt0;
            #pragma unroll
            for (int nt = 0; nt < 4; nt++) {
                const int col = nq*32 + nt*8 + c2;
                const int t   = tbase + nt*8 + c2;
                #pragma unroll
                for (int rr = 0; rr < 2; rr++) {
                    const int q = mt*16 + g + rr*8;
                    const float v0 = acc[u][nt][rr*2];
                    const float v1 = acc[u][nt][rr*2+1];
                    __half2 h2, l2;
                    split_f16(v0, h2.x, l2.x);
                    split_f16(v1, h2.y, l2.y);
                    if (q < NNODE)
                        *(__half2*)(Y1g + q*TSEQ + t) = h2;
                    *(__half2*)(sBH + q*SB2 + col) = h2;
                    *(__half2*)(sBL + q*SB2 + col) = l2;
                }
            }
        }
        __syncthreads();

        // ======== GEMM 2: Z = adj @ Y1 (raw) ========
        gemm_n128(aH, bHo, bLo, w, lane, acc);

        #pragma unroll
        for (int u = 0; u < 3; u++) {
            if (u == 2 && !hasC) break;
            const int mt = u*4 + mt0;
            #pragma unroll
            for (int nt = 0; nt < 4; nt++) {
                const int t = tbase + nt*8 + c2;
                #pragma unroll
                for (int rr = 0; rr < 2; rr++) {
                    const int q = mt*16 + g + rr*8;
                    if (q < NNODE) {
                        __half2 z2;
                        z2.x = __float2half_rn(acc[u][nt][rr*2]);
                        z2.y = __float2half_rn(acc[u][nt][rr*2+1]);
                        *(__half2*)(Zg + q*TSEQ + t) = z2;
                    }
                }
            }
        }
    }
}

// ---------------------------------------------------------------------------
// Persistent channel stage: 128 threads (4 warps = 2m-groups x 2n), 2 CTAs/SM.
// Single-pass K=256: out = W3cat @ [Xhi;Xlo;Y1;Z] + bias
// ---------------------------------------------------------------------------
__global__ __launch_bounds__(128, 2) void k_chan_pers(const float* __restrict__ x,
                                                      const float* __restrict__ bias,
                                                      float* __restrict__ out)
{
    extern __shared__ char smem[];
    const uint32_t sbase = smem_u32(smem);
    const uint32_t wH = sbase + WH_OFF;
    const uint32_t cB = sbase + CB_OFF;
    __half* sB = (__half*)(smem + CB_OFF);

    const int tid  = threadIdx.x;
    const int w    = tid >> 5;
    const int lane = tid & 31;
    const int wm   = w & 1;          // m half: o 0-31 / 32-63 (2 tiles each)
    const int wn   = w >> 1;         // n half: 32 pos each
    const int g    = lane >> 2;
    const int c2   = (lane & 3) * 2;
    const int brow_l = lane & 15;
    const int bcol_l = (lane >> 4) * 8;

    // ---- stage W3 image once per CTA ----
    {
        const float4* gh = (const float4*)g_W3h;
        float4* dh = (float4*)(smem + WH_OFF);
        for (int i = tid; i < (COUT*SW3*2)/16; i += 128) dh[i] = gh[i];
    }

    for (int it = blockIdx.x; it < CH_ITEMS; it += CH_GRID) {
        const int b  = it / (NT/PT2);
        const int p0 = (it % (NT/PT2)) * PT2;
        const float*  xb = x     + (size_t)b * BSTRIDE;
        const __half* yb = g_Y1h + (size_t)b * BSTRIDE;
        const __half* zb = g_Zh  + (size_t)b * BSTRIDE;

        __syncthreads();
        // ---- stage B: rows [0,64)=Xhi, [64,128)=Xlo, [128,192)=Y1, [192,256)=Z
        for (int idx = tid; idx < CIN*16; idx += 128) {       // X: split
            const int c  = idx >> 4;
            const int p4 = idx & 15;
            const float4 v = *(const float4*)(xb + (size_t)c*NT + p0 + p4*4);
            __half h0,l0,h1,l1,h2,l2,h3,l3;
            split_f16(v.x, h0, l0); split_f16(v.y, h1, l1);
            split_f16(v.z, h2, l2); split_f16(v.w, h3, l3);
            __half2 hh[2] = { {h0,h1}, {h2,h3} };
            __half2 ll[2] = { {l0,l1}, {l2,l3} };
            *(uint2*)(sB + c*SC2        + p4*4) = *(uint2*)hh;
            *(uint2*)(sB + (64+c)*SC2   + p4*4) = *(uint2*)ll;
        }
        for (int idx = tid; idx < CIN*16; idx += 128) {       // Y1, Z: copy
            const int c  = idx >> 4;
            const int p4 = idx & 15;
            *(uint2*)(sB + (128+c)*SC2 + p4*4) =
                *(const uint2*)(yb + (size_t)c*NT + p0 + p4*4);
            *(uint2*)(sB + (192+c)*SC2 + p4*4) =
                *(const uint2*)(zb + (size_t)c*NT + p0 + p4*4);
        }
        __syncthreads();

        // ---- GEMM: M=64, N=64, K=256, single pass ----
        float acc[2][4][4];
        #pragma unroll
        for (int mi = 0; mi < 2; mi++)
            #pragma unroll
            for (int ni = 0; ni < 4; ni++)
                #pragma unroll
                for (int p = 0; p < 4; p++) acc[mi][ni][p] = 0.0f;

        for (int k0 = 0; k0 < KC3; k0 += 16) {
            uint32_t bh[2][4];
            #pragma unroll
            for (int gB = 0; gB < 2; gB++) {
                const uint32_t bb =
                    (uint32_t)((k0 + brow_l)*SC2 + wn*32 + gB*16 + bcol_l) * 2;
                LDSM_X4T(bh[gB], cB + bb);
            }
            #pragma unroll
            for (int mi = 0; mi < 2; mi++) {
                uint32_t ah[4];
                const uint32_t ab =
                    (uint32_t)(((wm*2 + mi)*16 + brow_l)*SW3 + k0 + bcol_l) * 2;
                LDSM_X4(ah, wH + ab);
                #pragma unroll
                for (int gB = 0; gB < 2; gB++)
                    #pragma unroll
                    for (int s = 0; s < 2; s++) {
                        float* d = acc[mi][gB*2 + s];
                        MMA_F16(d, ah, bh[gB][s*2], bh[gB][s*2+1]);
                    }
            }
        }

        // ---- epilogue: bias + store ----
        float* outb = out + (size_t)b * (COUT*(size_t)NT);
        #pragma unroll
        for (int mi = 0; mi < 2; mi++)
            #pragma unroll
            for (int rr = 0; rr < 2; rr++) {
                const int o = (wm*2 + mi)*16 + g + rr*8;
                const float bv = __ldg(bias + o);
                #pragma unroll
                for (int ni = 0; ni < 4; ni++) {
                    const int pos = p0 + wn*32 + ni*8 + c2;
                    float2 r;
                    r.x = acc[mi][ni][rr*2]   + bv;
                    r.y = acc[mi][ni][rr*2+1] + bv;
                    *(float2*)(outb + (size_t)o*NT + pos) = r;
                }
            }
    }
}

// ---------------------------------------------------------------------------
extern "C" void kernel_launch(void* const* d_in, const int* in_sizes, int n_in,
                              void* d_out, int out_size)
{
    const float* x    = (const float*)d_in[0];
    const float* adj  = (const float*)d_in[1];
    const float* W    = (const float*)d_in[2];
    const float* bias = (const float*)d_in[3];
    float* out = (float*)d_out;

    cudaFuncSetAttribute(k_node_pers, cudaFuncAttributeMaxDynamicSharedMemorySize,
                         NODE_SMEM);
    cudaFuncSetAttribute(k_chan_pers, cudaFuncAttributeMaxDynamicSharedMemorySize,
                         CHAN_SMEM);

    k_prep_w3<<<(COUT*SW3 + 255)/256, 256>>>(W);
    k_prep_adj<<<(MPAD*SA + 255)/256, 256>>>(adj);
    k_node_pers<<<NODE_GRID, 512, NODE_SMEM>>>(x);
    k_chan_pers<<<CH_GRID, 128, CHAN_SMEM>>>(x, bias, out);
}

// round 17
// speedup vs baseline: 2.0933x; 1.0469x over previous
#include <cuda_runtime.h>
#include <cuda_fp16.h>
#include <cstdint>

#define NNODE 170
#define MPAD  176          // node dim padded to 11 m-tiles of 16
#define SA    184          // adj smem row stride (elems)
#define SB2   136          // node B tile row stride (elems), 128 cols used
#define TSEQ  64
#define CIN   64
#define COUT  64
#define BATCH 32
#define NT    (NNODE*TSEQ)          // 10880 = 85 * 128 = 170 * 64
#define BSTRIDE (CIN*NT)
#define NITEMS (BATCH*CIN)          // 2048
#define NPAIR  (NITEMS/2)           // 1024
#define NODE_GRID 148

#define KC3   256          // chan K: [Xhi;Xlo;Y1;Z] = 4*64
#define SW3   264          // W3 image row stride (elems)
#define SC3   136          // chan B tile row stride (elems), 128 cols used
#define PT3   128          // pos per chan item
#define CH_ITEMS (BATCH*(NT/PT3))   // 32*85 = 2720
#define CH_GRID 296                 // 2 CTAs per SM

typedef unsigned long long u64;

// ---------------- device scratch (no allocs allowed) -----------------------
__device__ __half g_Y1h[NITEMS*NT];              // fp16 Y1
__device__ __half g_Zh [NITEMS*NT];              // fp16 Z = adj@Y1
__device__ __align__(16) __half g_adjh[MPAD*SA]; // padded [176][184]
__device__ __align__(16) __half g_W3h[COUT*SW3]; // [o][k]: [Wx|Wx|Wy|2*W3]

// ---------------- node smem map (bytes) -------------------------------------
#define AH_OFF 0                        // 176*184*2 = 64768
#define BH_OFF 64768                    // 176*136*2 = 47872
#define BL_OFF 112640
#define NODE_SMEM 160512

// ---------------- chan smem map (bytes) -------------------------------------
#define WH_OFF 0                        // 64*264*2 = 33792
#define CB_OFF 33792                    // 256*136*2 = 69632
#define CHAN_SMEM 103424                // 2 CTAs/SM

// ---------------- helpers ---------------------------------------------------
__device__ __forceinline__ uint32_t smem_u32(const void* p) {
    uint32_t a;
    asm("{ .reg .u64 t; cvta.to.shared.u64 t, %1; cvt.u32.u64 %0, t; }"
        : "=r"(a) : "l"(p));
    return a;
}

#define LDSM_X4(r, addr) \
    asm volatile("ldmatrix.sync.aligned.m8n8.x4.shared.b16 {%0,%1,%2,%3}, [%4];" \
        : "=r"((r)[0]), "=r"((r)[1]), "=r"((r)[2]), "=r"((r)[3]) : "r"(addr))
#define LDSM_X4T(r, addr) \
    asm volatile("ldmatrix.sync.aligned.m8n8.x4.trans.shared.b16 {%0,%1,%2,%3}, [%4];" \
        : "=r"((r)[0]), "=r"((r)[1]), "=r"((r)[2]), "=r"((r)[3]) : "r"(addr))

#define MMA_F16(d, a, b0, b1) \
    asm volatile("mma.sync.aligned.m16n8k16.row.col.f32.f16.f16.f32 " \
        "{%0,%1,%2,%3}, {%4,%5,%6,%7}, {%8,%9}, {%0,%1,%2,%3};" \
        : "+f"((d)[0]), "+f"((d)[1]), "+f"((d)[2]), "+f"((d)[3]) \
        : "r"((a)[0]), "r"((a)[1]), "r"((a)[2]), "r"((a)[3]), "r"(b0), "r"(b1))

__device__ __forceinline__ void split_f16(float v, __half& h, __half& l) {
    h = __float2half_rn(v);
    l = __float2half_rn(v - __half2float(h));
}

// ---------------------------------------------------------------------------
// Prep kernels
// ---------------------------------------------------------------------------
__global__ void k_prep_w3(const float* __restrict__ W)
{
    int i = blockIdx.x * 256 + threadIdx.x;     // over 64*SW3
    if (i >= COUT*SW3) return;
    int o = i / SW3, k = i % SW3;
    float v = 0.0f;
    if (k < 128) {          // Wx = W1 - W3 (duplicated for Xhi and Xlo)
        int c = k & 63;
        v = W[o*192 + c*3 + 0] - W[o*192 + c*3 + 2];
    } else if (k < 192) {   // Wy = W2
        int c = k - 128;
        v = W[o*192 + c*3 + 1];
    } else if (k < KC3) {   // 2*W3
        int c = k - 192;
        v = 2.0f * W[o*192 + c*3 + 2];
    }
    g_W3h[i] = __float2half_rn(v);
}

__global__ void k_prep_adj(const float* __restrict__ adj)
{
    int i = blockIdx.x * 256 + threadIdx.x;
    if (i >= MPAD*SA) return;
    int q = i / SA, k = i % SA;
    float a = (q < NNODE && k < NNODE) ? adj[q*NNODE + k] : 0.0f;
    g_adjh[i] = __float2half_rn(a);
}

// ---------------------------------------------------------------------------
// Node GEMM, 2-item wide (N=128), fp16 2-pass (unchanged from R16)
// ---------------------------------------------------------------------------
__device__ __forceinline__ void gemm_n128(uint32_t aH,
                                          uint32_t bH, uint32_t bL,
                                          int w, int lane, float acc[3][4][4])
{
    #pragma unroll
    for (int u = 0; u < 3; u++)
        #pragma unroll
        for (int n = 0; n < 4; n++)
            #pragma unroll
            for (int p = 0; p < 4; p++) acc[u][n][p] = 0.0f;

    const int nq   = w & 3;
    const int mt0  = w >> 2;
    const bool hasC = (mt0 < 3);
    const int brow = lane & 15;
    const int bcol = (lane >> 4) * 8;

    for (int k0 = 0; k0 < MPAD; k0 += 16) {
        uint32_t bh[2][4], bl[2][4];
        #pragma unroll
        for (int gB = 0; gB < 2; gB++) {
            const uint32_t bb =
                (uint32_t)((k0 + brow)*SB2 + nq*32 + gB*16 + bcol) * 2;
            LDSM_X4T(bh[gB], bH + bb);
            LDSM_X4T(bl[gB], bL + bb);
        }
        #pragma unroll
        for (int u = 0; u < 3; u++) {
            if (u == 2 && !hasC) break;
            const int mt = u*4 + mt0;
            uint32_t ah[4];
            const uint32_t ab = (uint32_t)((mt*16 + brow)*SA + k0 + bcol) * 2;
            LDSM_X4(ah, aH + ab);
            #pragma unroll
            for (int gB = 0; gB < 2; gB++)
                #pragma unroll
                for (int s = 0; s < 2; s++) {
                    float* d = acc[u][gB*2 + s];
                    MMA_F16(d, ah, bh[gB][s*2], bh[gB][s*2+1]);
                    MMA_F16(d, ah, bl[gB][s*2], bl[gB][s*2+1]);
                }
        }
    }
}

// ---------------------------------------------------------------------------
// Persistent node stage, 2 items per iteration (unchanged from R16)
// ---------------------------------------------------------------------------
__global__ __launch_bounds__(512, 1) void k_node_pers(const float* __restrict__ x)
{
    extern __shared__ char smem[];
    const uint32_t sbase = smem_u32(smem);
    const uint32_t aH = sbase + AH_OFF;
    const uint32_t bHo = sbase + BH_OFF, bLo = sbase + BL_OFF;
    __half* sBH = (__half*)(smem + BH_OFF);
    __half* sBL = (__half*)(smem + BL_OFF);

    const int tid  = threadIdx.x;
    const int w    = tid >> 5;
    const int lane = tid & 31;
    const int g    = lane >> 2;
    const int c2   = (lane & 3) * 2;
    const int nq   = w & 3;
    const int mt0  = w >> 2;
    const bool hasC = (mt0 < 3);
    const int item = nq >> 1;
    const int tbase = nq*32 - item*64;

    {
        const float4* gh = (const float4*)g_adjh;
        float4* dh = (float4*)(smem + AH_OFF);
        for (int i = tid; i < (MPAD*SA*2)/16; i += 512) dh[i] = gh[i];
    }
    for (int i = tid; i < (MPAD - NNODE)*SB2; i += 512) {
        const int idx = NNODE*SB2 + i;
        sBH[idx] = __float2half_rn(0.f);
        sBL[idx] = __float2half_rn(0.f);
    }

    float acc[3][4][4];

    for (int it2 = blockIdx.x; it2 < NPAIR; it2 += NODE_GRID) {
        const float* Xg0 = x + (size_t)(it2*2) * NT;
        __half* Y1g = g_Y1h + (size_t)(it2*2 + item) * NT;
        __half* Zg  = g_Zh  + (size_t)(it2*2 + item) * NT;

        __syncthreads();
        for (int idx = tid; idx < NNODE*32; idx += 512) {
            const int n   = idx >> 5;
            const int c4  = idx & 31;
            const int itm = c4 >> 4;
            const int t4  = c4 & 15;
            const float4 v = __ldg((const float4*)(Xg0 + (size_t)itm*NT + n*TSEQ) + t4);
            __half h0,l0,h1,l1,h2,l2,h3,l3;
            split_f16(v.x, h0, l0); split_f16(v.y, h1, l1);
            split_f16(v.z, h2, l2); split_f16(v.w, h3, l3);
            __half2 hh[2] = { {h0,h1}, {h2,h3} };
            __half2 ll[2] = { {l0,l1}, {l2,l3} };
            *(uint2*)(sBH + n*SB2 + c4*4) = *(uint2*)hh;
            *(uint2*)(sBL + n*SB2 + c4*4) = *(uint2*)ll;
        }
        __syncthreads();

        gemm_n128(aH, bHo, bLo, w, lane, acc);
        __syncthreads();

        #pragma unroll
        for (int u = 0; u < 3; u++) {
            if (u == 2 && !hasC) break;
            const int mt = u*4 + mt0;
            #pragma unroll
            for (int nt = 0; nt < 4; nt++) {
                const int col = nq*32 + nt*8 + c2;
                const int t   = tbase + nt*8 + c2;
                #pragma unroll
                for (int rr = 0; rr < 2; rr++) {
                    const int q = mt*16 + g + rr*8;
                    const float v0 = acc[u][nt][rr*2];
                    const float v1 = acc[u][nt][rr*2+1];
                    __half2 h2, l2;
                    split_f16(v0, h2.x, l2.x);
                    split_f16(v1, h2.y, l2.y);
                    if (q < NNODE)
                        *(__half2*)(Y1g + q*TSEQ + t) = h2;
                    *(__half2*)(sBH + q*SB2 + col) = h2;
                    *(__half2*)(sBL + q*SB2 + col) = l2;
                }
            }
        }
        __syncthreads();

        gemm_n128(aH, bHo, bLo, w, lane, acc);

        #pragma unroll
        for (int u = 0; u < 3; u++) {
            if (u == 2 && !hasC) break;
            const int mt = u*4 + mt0;
            #pragma unroll
            for (int nt = 0; nt < 4; nt++) {
                const int t = tbase + nt*8 + c2;
                #pragma unroll
                for (int rr = 0; rr < 2; rr++) {
                    const int q = mt*16 + g + rr*8;
                    if (q < NNODE) {
                        __half2 z2;
                        z2.x = __float2half_rn(acc[u][nt][rr*2]);
                        z2.y = __float2half_rn(acc[u][nt][rr*2+1]);
                        *(__half2*)(Zg + q*TSEQ + t) = z2;
                    }
                }
            }
        }
    }
}

// ---------------------------------------------------------------------------
// Persistent channel stage: 128 threads (4 warps = 2m x 2n), 2 CTAs/SM,
// 128-pos items. Warp = 2 m-tiles x 64 pos (256 MMA/item, 16 MMA per 6 ldsm).
// Single-pass K=256: out = W3cat @ [Xhi;Xlo;Y1;Z] + bias
// ---------------------------------------------------------------------------
__global__ __launch_bounds__(128, 2) void k_chan_pers(const float* __restrict__ x,
                                                      const float* __restrict__ bias,
                                                      float* __restrict__ out)
{
    extern __shared__ char smem[];
    const uint32_t sbase = smem_u32(smem);
    const uint32_t wH = sbase + WH_OFF;
    const uint32_t cB = sbase + CB_OFF;
    __half* sB = (__half*)(smem + CB_OFF);

    const int tid  = threadIdx.x;
    const int w    = tid >> 5;
    const int lane = tid & 31;
    const int wm   = w & 1;          // m half: o 0-31 / 32-63 (2 tiles each)
    const int wn   = w >> 1;         // n half: 64 pos each
    const int g    = lane >> 2;
    const int c2   = (lane & 3) * 2;
    const int brow_l = lane & 15;
    const int bcol_l = (lane >> 4) * 8;

    // ---- stage W3 image once per CTA ----
    {
        const float4* gh = (const float4*)g_W3h;
        float4* dh = (float4*)(smem + WH_OFF);
        for (int i = tid; i < (COUT*SW3*2)/16; i += 128) dh[i] = gh[i];
    }

    for (int it = blockIdx.x; it < CH_ITEMS; it += CH_GRID) {
        const int b  = it / (NT/PT3);
        const int p0 = (it % (NT/PT3)) * PT3;
        const float*  xb = x     + (size_t)b * BSTRIDE;
        const __half* yb = g_Y1h + (size_t)b * BSTRIDE;
        const __half* zb = g_Zh  + (size_t)b * BSTRIDE;

        __syncthreads();
        // ---- stage B: rows [0,64)=Xhi, [64,128)=Xlo, [128,192)=Y1, [192,256)=Z
        for (int idx = tid; idx < CIN*32; idx += 128) {       // X: split, 128 cols
            const int c  = idx >> 5;
            const int p4 = idx & 31;
            const float4 v = *(const float4*)(xb + (size_t)c*NT + p0 + p4*4);
            __half h0,l0,h1,l1,h2,l2,h3,l3;
            split_f16(v.x, h0, l0); split_f16(v.y, h1, l1);
            split_f16(v.z, h2, l2); split_f16(v.w, h3, l3);
            __half2 hh[2] = { {h0,h1}, {h2,h3} };
            __half2 ll[2] = { {l0,l1}, {l2,l3} };
            *(uint2*)(sB + c*SC3        + p4*4) = *(uint2*)hh;
            *(uint2*)(sB + (64+c)*SC3   + p4*4) = *(uint2*)ll;
        }
        for (int idx = tid; idx < CIN*16; idx += 128) {       // Y1, Z: uint4 copy
            const int c  = idx >> 4;
            const int p8 = idx & 15;
            *(uint4*)(sB + (128+c)*SC3 + p8*8) =
                *(const uint4*)(yb + (size_t)c*NT + p0 + p8*8);
            *(uint4*)(sB + (192+c)*SC3 + p8*8) =
                *(const uint4*)(zb + (size_t)c*NT + p0 + p8*8);
        }
        __syncthreads();

        // ---- GEMM: M=64, N=128, K=256, single pass ----
        float acc[2][8][4];
        #pragma unroll
        for (int mi = 0; mi < 2; mi++)
            #pragma unroll
            for (int ni = 0; ni < 8; ni++)
                #pragma unroll
                for (int p = 0; p < 4; p++) acc[mi][ni][p] = 0.0f;

        for (int k0 = 0; k0 < KC3; k0 += 16) {
            uint32_t bh[4][4];
            #pragma unroll
            for (int gB = 0; gB < 4; gB++) {
                const uint32_t bb =
                    (uint32_t)((k0 + brow_l)*SC3 + wn*64 + gB*16 + bcol_l) * 2;
                LDSM_X4T(bh[gB], cB + bb);
            }
            #pragma unroll
            for (int mi = 0; mi < 2; mi++) {
                uint32_t ah[4];
                const uint32_t ab =
                    (uint32_t)(((wm*2 + mi)*16 + brow_l)*SW3 + k0 + bcol_l) * 2;
                LDSM_X4(ah, wH + ab);
                #pragma unroll
                for (int gB = 0; gB < 4; gB++)
                    #pragma unroll
                    for (int s = 0; s < 2; s++) {
                        float* d = acc[mi][gB*2 + s];
                        MMA_F16(d, ah, bh[gB][s*2], bh[gB][s*2+1]);
                    }
            }
        }

        // ---- epilogue: bias + store ----
        float* outb = out + (size_t)b * (COUT*(size_t)NT);
        #pragma unroll
        for (int mi = 0; mi < 2; mi++)
            #pragma unroll
            for (int rr = 0; rr < 2; rr++) {
                const int o = (wm*2 + mi)*16 + g + rr*8;
                const float bv = __ldg(bias + o);
                #pragma unroll
                for (int ni = 0; ni < 8; ni++) {
                    const int pos = p0 + wn*64 + ni*8 + c2;
                    float2 r;
                    r.x = acc[mi][ni][rr*2]   + bv;
                    r.y = acc[mi][ni][rr*2+1] + bv;
                    *(float2*)(outb + (size_t)o*NT + pos) = r;
                }
            }
    }
}

// ---------------------------------------------------------------------------
extern "C" void kernel_launch(void* const* d_in, const int* in_sizes, int n_in,
                              void* d_out, int out_size)
{
    const float* x    = (const float*)d_in[0];
    const float* adj  = (const float*)d_in[1];
    const float* W    = (const float*)d_in[2];
    const float* bias = (const float*)d_in[3];
    float* out = (float*)d_out;

    cudaFuncSetAttribute(k_node_pers, cudaFuncAttributeMaxDynamicSharedMemorySize,
                         NODE_SMEM);
    cudaFuncSetAttribute(k_chan_pers, cudaFuncAttributeMaxDynamicSharedMemorySize,
                         CHAN_SMEM);

    k_prep_w3<<<(COUT*SW3 + 255)/256, 256>>>(W);
    k_prep_adj<<<(MPAD*SA + 255)/256, 256>>>(adj);
    k_node_pers<<<NODE_GRID, 512, NODE_SMEM>>>(x);
    k_chan_pers<<<CH_GRID, 128, CHAN_SMEM>>>(x, bias, out);
}